// round 2
// baseline (speedup 1.0000x reference)
#include <cuda_runtime.h>

#define N_NODES 100000
#define N_EDGES 1600000
#define IN_DIM 256
#define HID 128
#define OUTD 64

// ---------------- scratch (device globals; no allocs allowed) ----------------
__device__ float g_deg[N_NODES];
__device__ float g_dinv[N_NODES];
__device__ float g_h1[(size_t)N_NODES * HID];   // x @ W1
__device__ float g_a1[(size_t)N_NODES * HID];   // aggregated layer-1 (pre bias/relu)
__device__ float g_h2[(size_t)N_NODES * OUTD];  // relu(a1+b1) @ W2

// ---------------- degree / normalization ----------------
__global__ void k_deg_init() {
    int i = blockIdx.x * blockDim.x + threadIdx.x;
    if (i < N_NODES) g_deg[i] = 1.0f;  // self-loop weight
}

__global__ void k_deg_edges(const int* __restrict__ col,
                            const float* __restrict__ w) {
    int e = blockIdx.x * blockDim.x + threadIdx.x;
    if (e < N_EDGES) atomicAdd(&g_deg[col[e]], w[e]);
}

__global__ void k_dinv() {
    int i = blockIdx.x * blockDim.x + threadIdx.x;
    if (i < N_NODES) {
        float d = g_deg[i];
        g_dinv[i] = d > 0.0f ? rsqrtf(d) : 0.0f;
    }
}

// ---------------- GEMM1: h1 = x @ W1   [100000,256]@[256,128] ----------------
// 256 threads/block, 32 rows/block (100000 % 32 == 0 -> exact grid 3125).
// thread: n = tid&127 (output col), row group = tid>>7 (16 rows each).
__global__ void __launch_bounds__(256) k_gemm1(const float* __restrict__ x,
                                               const float* __restrict__ W) {
    __shared__ float Ws[64 * HID];   // 32 KB: K-tile of W1, [kk][n]
    __shared__ float xs[32 * 64];    // 8 KB:  x tile, [r][kk]
    int tid = threadIdx.x;
    int n = tid & 127;
    int rbase = (tid >> 7) * 16;
    int row0 = blockIdx.x * 32;

    float acc[16];
#pragma unroll
    for (int r = 0; r < 16; r++) acc[r] = 0.0f;

    for (int kt = 0; kt < IN_DIM; kt += 64) {
        // W1 is row-major [256][128]; Ws[i] = W[kt*128 + i]
#pragma unroll
        for (int i = tid; i < 64 * HID; i += 256) Ws[i] = W[kt * HID + i];
#pragma unroll
        for (int i = tid; i < 32 * 64; i += 256) {
            int r = i >> 6, k = i & 63;
            xs[i] = x[(size_t)(row0 + r) * IN_DIM + kt + k];
        }
        __syncthreads();

#pragma unroll
        for (int kk = 0; kk < 64; kk += 4) {
            float w0 = Ws[(kk + 0) * HID + n];
            float w1 = Ws[(kk + 1) * HID + n];
            float w2 = Ws[(kk + 2) * HID + n];
            float w3 = Ws[(kk + 3) * HID + n];
#pragma unroll
            for (int r = 0; r < 16; r++) {
                float4 xv = *(const float4*)&xs[(rbase + r) * 64 + kk];
                acc[r] = fmaf(xv.x, w0, acc[r]);
                acc[r] = fmaf(xv.y, w1, acc[r]);
                acc[r] = fmaf(xv.z, w2, acc[r]);
                acc[r] = fmaf(xv.w, w3, acc[r]);
            }
        }
        __syncthreads();
    }

#pragma unroll
    for (int r = 0; r < 16; r++)
        g_h1[(size_t)(row0 + rbase + r) * HID + n] = acc[r];
}

// ---------------- layer-1 self-loop init: a1 = dinv^2 * h1 ----------------
__global__ void k_selfinit1() {
    int idx = blockIdx.x * blockDim.x + threadIdx.x;  // one float4, N*32 total
    if (idx >= N_NODES * 32) return;
    int node = idx >> 5;
    float s = g_dinv[node];
    s *= s;
    float4 v = ((const float4*)g_h1)[idx];
    v.x *= s; v.y *= s; v.z *= s; v.w *= s;
    ((float4*)g_a1)[idx] = v;
}

// ---------------- layer-1 edge scatter: warp per edge, 128 dims ----------------
__global__ void k_scatter1(const int* __restrict__ row,
                           const int* __restrict__ col,
                           const float* __restrict__ w) {
    int t = blockIdx.x * blockDim.x + threadIdx.x;
    int e = t >> 5;
    if (e >= N_EDGES) return;
    int lane = t & 31;
    int r = row[e], c = col[e];
    float norm = g_dinv[r] * w[e] * g_dinv[c];
    float4 v = ((const float4*)(g_h1 + (size_t)r * HID))[lane];
    float* ap = g_a1 + (size_t)c * HID + lane * 4;
    atomicAdd(ap + 0, norm * v.x);
    atomicAdd(ap + 1, norm * v.y);
    atomicAdd(ap + 2, norm * v.z);
    atomicAdd(ap + 3, norm * v.w);
}

// ---------------- GEMM2: h2 = relu(a1 + b1) @ W2  [100000,128]@[128,64] ------
// 256 threads/block, 16 rows/block (grid 6250). n = tid&63, 4 rows per thread.
__global__ void __launch_bounds__(256) k_gemm2(const float* __restrict__ W2,
                                               const float* __restrict__ b1) {
    __shared__ float Ws[HID * OUTD];  // 32 KB, full W2 [k][n]
    __shared__ float xs[16 * HID];    // 8 KB
    int tid = threadIdx.x;
    int n = tid & 63;
    int rbase = (tid >> 6) * 4;
    int row0 = blockIdx.x * 16;

#pragma unroll
    for (int i = tid; i < HID * OUTD; i += 256) Ws[i] = W2[i];
#pragma unroll
    for (int i = tid; i < 16 * HID; i += 256) {
        int r = i >> 7, k = i & 127;
        xs[i] = fmaxf(g_a1[(size_t)(row0 + r) * HID + k] + __ldg(&b1[k]), 0.0f);
    }
    __syncthreads();

    float acc[4] = {0.f, 0.f, 0.f, 0.f};
#pragma unroll
    for (int k = 0; k < HID; k += 4) {
        float w0 = Ws[(k + 0) * OUTD + n];
        float w1 = Ws[(k + 1) * OUTD + n];
        float w2 = Ws[(k + 2) * OUTD + n];
        float w3 = Ws[(k + 3) * OUTD + n];
#pragma unroll
        for (int r = 0; r < 4; r++) {
            float4 xv = *(const float4*)&xs[(rbase + r) * HID + k];
            acc[r] = fmaf(xv.x, w0, acc[r]);
            acc[r] = fmaf(xv.y, w1, acc[r]);
            acc[r] = fmaf(xv.z, w2, acc[r]);
            acc[r] = fmaf(xv.w, w3, acc[r]);
        }
    }
#pragma unroll
    for (int r = 0; r < 4; r++)
        g_h2[(size_t)(row0 + rbase + r) * OUTD + n] = acc[r];
}

// ---------------- output init: out = dinv^2 * h2 + b2 ----------------
__global__ void k_outinit(const float* __restrict__ b2, float* __restrict__ out) {
    int idx = blockIdx.x * blockDim.x + threadIdx.x;  // one float4, N*16 total
    if (idx >= N_NODES * 16) return;
    int node = idx >> 4;
    int dq = idx & 15;
    float s = g_dinv[node];
    s *= s;
    float4 v = ((const float4*)g_h2)[idx];
    float4 bb = ((const float4*)b2)[dq];
    v.x = fmaf(v.x, s, bb.x);
    v.y = fmaf(v.y, s, bb.y);
    v.z = fmaf(v.z, s, bb.z);
    v.w = fmaf(v.w, s, bb.w);
    ((float4*)out)[idx] = v;
}

// ---------------- layer-2 edge scatter: 16 lanes per edge, 64 dims ------------
__global__ void k_scatter2(const int* __restrict__ row,
                           const int* __restrict__ col,
                           const float* __restrict__ w,
                           float* __restrict__ out) {
    int t = blockIdx.x * blockDim.x + threadIdx.x;
    int e = t >> 4;
    if (e >= N_EDGES) return;
    int q = t & 15;
    int r = row[e], c = col[e];
    float norm = g_dinv[r] * w[e] * g_dinv[c];
    float4 v = ((const float4*)(g_h2 + (size_t)r * OUTD))[q];
    float* ap = out + (size_t)c * OUTD + q * 4;
    atomicAdd(ap + 0, norm * v.x);
    atomicAdd(ap + 1, norm * v.y);
    atomicAdd(ap + 2, norm * v.z);
    atomicAdd(ap + 3, norm * v.w);
}

// ---------------- launch ----------------
extern "C" void kernel_launch(void* const* d_in, const int* in_sizes, int n_in,
                              void* d_out, int out_size) {
    const float* x  = (const float*)d_in[0];
    const int*   ei = (const int*)d_in[1];   // int32! (JAX silently downgrades int64)
    const float* ew = (const float*)d_in[2];
    const float* W1 = (const float*)d_in[3];
    const float* b1 = (const float*)d_in[4];
    const float* W2 = (const float*)d_in[5];
    const float* b2 = (const float*)d_in[6];
    float*       out = (float*)d_out;

    const int* row = ei;            // edge_index[0]
    const int* col = ei + N_EDGES;  // edge_index[1]

    k_deg_init<<<(N_NODES + 255) / 256, 256>>>();
    k_deg_edges<<<(N_EDGES + 255) / 256, 256>>>(col, ew);
    k_dinv<<<(N_NODES + 255) / 256, 256>>>();

    k_gemm1<<<N_NODES / 32, 256>>>(x, W1);
    k_selfinit1<<<(N_NODES * 32) / 256 + 1, 256>>>();
    k_scatter1<<<(N_EDGES * 32) / 256, 256>>>(row, col, ew);

    k_gemm2<<<N_NODES / 16, 256>>>(W2, b1);
    k_outinit<<<(N_NODES * 16) / 256 + 1, 256>>>(b2, out);
    k_scatter2<<<(N_EDGES * 16) / 256, 256>>>(row, col, ew, out);
}

// round 3
// speedup vs baseline: 1.7666x; 1.7666x over previous
#include <cuda_runtime.h>

#define N_NODES 100000
#define N_EDGES 1600000
#define IN_DIM 256
#define HID 128
#define OUTD 64

// ---------------- scratch (device globals; no allocs allowed) ----------------
__device__ float g_deg[N_NODES];
__device__ float g_dinv[N_NODES];
__device__ float g_h1[(size_t)N_NODES * HID];   // dinv * (x @ W1)   (pre-scaled)
__device__ float g_a1[(size_t)N_NODES * HID];   // aggregated layer-1 (pre bias/relu)
__device__ float g_h2[(size_t)N_NODES * OUTD];  // dinv * (relu(a1+b1) @ W2)

// vector atomic add (sm_90+): 16B red to global
__device__ __forceinline__ void red_add_v4(float* p, float a, float b, float c, float d) {
    asm volatile("red.global.add.v4.f32 [%0], {%1,%2,%3,%4};"
                 :: "l"(__cvta_generic_to_global(p)), "f"(a), "f"(b), "f"(c), "f"(d)
                 : "memory");
}

// ---------------- degree / normalization ----------------
__global__ void k_deg_init() {
    int i = blockIdx.x * blockDim.x + threadIdx.x;
    if (i < N_NODES) g_deg[i] = 1.0f;  // self-loop weight
}

__global__ void k_deg_edges(const int* __restrict__ col,
                            const float* __restrict__ w) {
    int e = blockIdx.x * blockDim.x + threadIdx.x;
    if (e < N_EDGES) atomicAdd(&g_deg[col[e]], w[e]);
}

__global__ void k_dinv() {
    int i = blockIdx.x * blockDim.x + threadIdx.x;
    if (i < N_NODES) {
        float d = g_deg[i];
        g_dinv[i] = d > 0.0f ? rsqrtf(d) : 0.0f;
    }
}

// ---------------- GEMM1: 8x8 register-tiled SGEMM ----------------
// C[100000,128] = x[100000,256] @ W1[256,128]
// BM=64 BN=128 BK=16, 128 threads, thread tile 8x8.
// Epilogue: g_h1 = dinv*C, g_a1 = dinv^2*C (self-loop init).
__global__ void __launch_bounds__(128) k_gemm1(const float* __restrict__ x,
                                               const float* __restrict__ W) {
    __shared__ float As[16][64];    // [k][m]
    __shared__ float Bs[16][128];   // [k][n]
    int tid = threadIdx.x;
    int tx = tid & 15;   // n group: cols tx*8 .. +8
    int ty = tid >> 4;   // m group: rows ty*8 .. +8
    int row0 = blockIdx.x * 64;

    float acc[8][8];
#pragma unroll
    for (int i = 0; i < 8; i++)
#pragma unroll
        for (int j = 0; j < 8; j++) acc[i][j] = 0.0f;

    for (int kt = 0; kt < IN_DIM; kt += 16) {
        // A tile: 64 rows x 16 k. Each thread: 2 float4, transposed store.
        {
            int ar = tid >> 1;
            int af = (tid & 1) * 2;
            int grow = row0 + ar;
            const float* src = x + (size_t)grow * IN_DIM + kt;
#pragma unroll
            for (int j = 0; j < 2; j++) {
                float4 v = make_float4(0.f, 0.f, 0.f, 0.f);
                if (grow < N_NODES) v = *(const float4*)(src + (af + j) * 4);
                int kk = (af + j) * 4;
                As[kk + 0][ar] = v.x;
                As[kk + 1][ar] = v.y;
                As[kk + 2][ar] = v.z;
                As[kk + 3][ar] = v.w;
            }
        }
        // B tile: 16 rows x 128 cols = 512 float4, 4 per thread.
#pragma unroll
        for (int j = 0; j < 4; j++) {
            int idx = tid + j * 128;
            int br = idx >> 5;
            int bc = (idx & 31) * 4;
            *(float4*)&Bs[br][bc] = *(const float4*)(W + (size_t)(kt + br) * HID + bc);
        }
        __syncthreads();

#pragma unroll
        for (int kk = 0; kk < 16; kk++) {
            float4 a0 = *(float4*)&As[kk][ty * 8];
            float4 a1 = *(float4*)&As[kk][ty * 8 + 4];
            float4 b0 = *(float4*)&Bs[kk][tx * 8];
            float4 b1 = *(float4*)&Bs[kk][tx * 8 + 4];
            float am[8] = {a0.x, a0.y, a0.z, a0.w, a1.x, a1.y, a1.z, a1.w};
            float bn[8] = {b0.x, b0.y, b0.z, b0.w, b1.x, b1.y, b1.z, b1.w};
#pragma unroll
            for (int i = 0; i < 8; i++)
#pragma unroll
                for (int j = 0; j < 8; j++)
                    acc[i][j] = fmaf(am[i], bn[j], acc[i][j]);
        }
        __syncthreads();
    }

#pragma unroll
    for (int i = 0; i < 8; i++) {
        int grow = row0 + ty * 8 + i;
        if (grow >= N_NODES) break;
        float s = g_dinv[grow];
        float s2 = s * s;
        float* hp = g_h1 + (size_t)grow * HID + tx * 8;
        float* ap = g_a1 + (size_t)grow * HID + tx * 8;
        float4 h0 = make_float4(s * acc[i][0], s * acc[i][1], s * acc[i][2], s * acc[i][3]);
        float4 h1v = make_float4(s * acc[i][4], s * acc[i][5], s * acc[i][6], s * acc[i][7]);
        float4 a0 = make_float4(s2 * acc[i][0], s2 * acc[i][1], s2 * acc[i][2], s2 * acc[i][3]);
        float4 a1v = make_float4(s2 * acc[i][4], s2 * acc[i][5], s2 * acc[i][6], s2 * acc[i][7]);
        *(float4*)(hp) = h0;
        *(float4*)(hp + 4) = h1v;
        *(float4*)(ap) = a0;
        *(float4*)(ap + 4) = a1v;
    }
}

// ---------------- layer-1 edge scatter: warp per edge, v4 red ----------------
// msg = w[e]*dinv[c] * h1'[r]   (h1' already carries dinv[r])
__global__ void k_scatter1(const int* __restrict__ row,
                           const int* __restrict__ col,
                           const float* __restrict__ w) {
    int t = blockIdx.x * blockDim.x + threadIdx.x;
    int e = t >> 5;
    if (e >= N_EDGES) return;
    int lane = t & 31;
    int r = row[e], c = col[e];
    float norm = w[e] * g_dinv[c];
    float4 v = ((const float4*)(g_h1 + (size_t)r * HID))[lane];
    float* ap = g_a1 + (size_t)c * HID + lane * 4;
    red_add_v4(ap, norm * v.x, norm * v.y, norm * v.z, norm * v.w);
}

// ---------------- GEMM2: C = relu(a1+b1) @ W2,  [100000,128]@[128,64] --------
// BM=64 BN=64 BK=32, 128 threads, thread tile 4x8.
// Epilogue: g_h2 = dinv*C, out = dinv^2*C + b2.
__global__ void __launch_bounds__(128) k_gemm2(const float* __restrict__ W2,
                                               const float* __restrict__ b1,
                                               const float* __restrict__ b2,
                                               float* __restrict__ out) {
    __shared__ float As[32][64];   // [k][m]
    __shared__ float Bs[32][64];   // [k][n]
    __shared__ float b1s[HID];
    __shared__ float b2s[OUTD];
    int tid = threadIdx.x;
    int tx = tid & 7;    // n group: cols tx*8
    int ty = tid >> 3;   // m group: rows ty*4 (0..15)
    int row0 = blockIdx.x * 64;

    if (tid < HID) b1s[tid] = b1[tid];
    if (tid < OUTD) b2s[tid] = b2[tid];
    __syncthreads();

    float acc[4][8];
#pragma unroll
    for (int i = 0; i < 4; i++)
#pragma unroll
        for (int j = 0; j < 8; j++) acc[i][j] = 0.0f;

    for (int kt = 0; kt < HID; kt += 32) {
        // A tile: 64 rows x 32 k, bias+relu applied. 512 float4, 4/thread.
        {
            int ar = tid >> 1;
            int grow = row0 + ar;
            const float* src = g_a1 + (size_t)grow * HID + kt;
#pragma unroll
            for (int j = 0; j < 4; j++) {
                int f4 = (tid & 1) * 4 + j;   // 0..7
                int kk = f4 * 4;
                float4 v = make_float4(0.f, 0.f, 0.f, 0.f);
                if (grow < N_NODES) {
                    v = *(const float4*)(src + kk);
                    v.x = fmaxf(v.x + b1s[kt + kk + 0], 0.f);
                    v.y = fmaxf(v.y + b1s[kt + kk + 1], 0.f);
                    v.z = fmaxf(v.z + b1s[kt + kk + 2], 0.f);
                    v.w = fmaxf(v.w + b1s[kt + kk + 3], 0.f);
                }
                As[kk + 0][ar] = v.x;
                As[kk + 1][ar] = v.y;
                As[kk + 2][ar] = v.z;
                As[kk + 3][ar] = v.w;
            }
        }
        // B tile: 32 rows x 64 cols = 512 float4, 4/thread.
#pragma unroll
        for (int j = 0; j < 4; j++) {
            int idx = tid + j * 128;
            int br = idx >> 4;
            int bc = (idx & 15) * 4;
            *(float4*)&Bs[br][bc] = *(const float4*)(W2 + (size_t)(kt + br) * OUTD + bc);
        }
        __syncthreads();

#pragma unroll
        for (int kk = 0; kk < 32; kk++) {
            float4 a = *(float4*)&As[kk][ty * 4];
            float4 b0 = *(float4*)&Bs[kk][tx * 8];
            float4 b1v = *(float4*)&Bs[kk][tx * 8 + 4];
            float am[4] = {a.x, a.y, a.z, a.w};
            float bn[8] = {b0.x, b0.y, b0.z, b0.w, b1v.x, b1v.y, b1v.z, b1v.w};
#pragma unroll
            for (int i = 0; i < 4; i++)
#pragma unroll
                for (int j = 0; j < 8; j++)
                    acc[i][j] = fmaf(am[i], bn[j], acc[i][j]);
        }
        __syncthreads();
    }

#pragma unroll
    for (int i = 0; i < 4; i++) {
        int grow = row0 + ty * 4 + i;
        if (grow >= N_NODES) break;
        float s = g_dinv[grow];
        float s2 = s * s;
        int nc = tx * 8;
        float* hp = g_h2 + (size_t)grow * OUTD + nc;
        float* op = out + (size_t)grow * OUTD + nc;
        float4 h0 = make_float4(s * acc[i][0], s * acc[i][1], s * acc[i][2], s * acc[i][3]);
        float4 h1v = make_float4(s * acc[i][4], s * acc[i][5], s * acc[i][6], s * acc[i][7]);
        float4 o0 = make_float4(s2 * acc[i][0] + b2s[nc + 0], s2 * acc[i][1] + b2s[nc + 1],
                                s2 * acc[i][2] + b2s[nc + 2], s2 * acc[i][3] + b2s[nc + 3]);
        float4 o1 = make_float4(s2 * acc[i][4] + b2s[nc + 4], s2 * acc[i][5] + b2s[nc + 5],
                                s2 * acc[i][6] + b2s[nc + 6], s2 * acc[i][7] + b2s[nc + 7]);
        *(float4*)(hp) = h0;
        *(float4*)(hp + 4) = h1v;
        *(float4*)(op) = o0;
        *(float4*)(op + 4) = o1;
    }
}

// ---------------- layer-2 edge scatter: 16 lanes per edge, v4 red ------------
__global__ void k_scatter2(const int* __restrict__ row,
                           const int* __restrict__ col,
                           const float* __restrict__ w,
                           float* __restrict__ out) {
    int t = blockIdx.x * blockDim.x + threadIdx.x;
    int e = t >> 4;
    if (e >= N_EDGES) return;
    int q = t & 15;
    int r = row[e], c = col[e];
    float norm = w[e] * g_dinv[c];
    float4 v = ((const float4*)(g_h2 + (size_t)r * OUTD))[q];
    float* ap = out + (size_t)c * OUTD + q * 4;
    red_add_v4(ap, norm * v.x, norm * v.y, norm * v.z, norm * v.w);
}

// ---------------- launch ----------------
extern "C" void kernel_launch(void* const* d_in, const int* in_sizes, int n_in,
                              void* d_out, int out_size) {
    const float* x  = (const float*)d_in[0];
    const int*   ei = (const int*)d_in[1];   // int32 (JAX downgrades int64)
    const float* ew = (const float*)d_in[2];
    const float* W1 = (const float*)d_in[3];
    const float* b1 = (const float*)d_in[4];
    const float* W2 = (const float*)d_in[5];
    const float* b2 = (const float*)d_in[6];
    float*       out = (float*)d_out;

    const int* row = ei;            // edge_index[0]
    const int* col = ei + N_EDGES;  // edge_index[1]

    k_deg_init<<<(N_NODES + 255) / 256, 256>>>();
    k_deg_edges<<<(N_EDGES + 255) / 256, 256>>>(col, ew);
    k_dinv<<<(N_NODES + 255) / 256, 256>>>();

    k_gemm1<<<(N_NODES + 63) / 64, 128>>>(x, W1);
    k_scatter1<<<(N_EDGES * 32) / 256, 256>>>(row, col, ew);

    k_gemm2<<<(N_NODES + 63) / 64, 128>>>(W2, b1, b2, out);
    k_scatter2<<<(N_EDGES * 16) / 256, 256>>>(row, col, ew, out);
}

// round 4
// speedup vs baseline: 2.5985x; 1.4709x over previous
#include <cuda_runtime.h>

#define N_NODES 100000
#define N_EDGES 1600000
#define IN_DIM 256
#define HID 128
#define OUTD 64

// ---------------- scratch (device globals; no allocs allowed) ----------------
__device__ float g_deg[N_NODES];
__device__ float g_dinv[N_NODES];
__device__ int   g_cnt[N_NODES];
__device__ int   g_off[N_NODES];
__device__ int   g_cur[N_NODES];
__device__ int   g_total;
__device__ int   g_src[N_EDGES];    // CSR: source node per (sorted-by-target) edge
__device__ float g_we[N_EDGES];     // CSR: edge weight
__device__ float g_h1[(size_t)N_NODES * HID];   // dinv * (x @ W1)
__device__ float g_a1[(size_t)N_NODES * HID];   // aggregated layer-1 (pre bias/relu)
__device__ float g_h2[(size_t)N_NODES * OUTD];  // dinv * (relu(a1+b1) @ W2)

__device__ __forceinline__ void cp_async16(void* smem, const void* gmem) {
    unsigned s = (unsigned)__cvta_generic_to_shared(smem);
    asm volatile("cp.async.cg.shared.global [%0], [%1], 16;" :: "r"(s), "l"(gmem));
}
#define CP_COMMIT() asm volatile("cp.async.commit_group;")
#define CP_WAIT0()  asm volatile("cp.async.wait_group 0;")

// ---------------- init / degree / normalization ----------------
__global__ void k_init() {
    int i = blockIdx.x * blockDim.x + threadIdx.x;
    if (i < N_NODES) { g_deg[i] = 1.0f; g_cnt[i] = 0; }
    if (i == 0) g_total = 0;
}

__global__ void k_hist(const int* __restrict__ col, const float* __restrict__ w) {
    int e = blockIdx.x * blockDim.x + threadIdx.x;
    if (e < N_EDGES) {
        int c = col[e];
        atomicAdd(&g_deg[c], w[e]);
        atomicAdd(&g_cnt[c], 1);
    }
}

__global__ void k_dinv() {
    int i = blockIdx.x * blockDim.x + threadIdx.x;
    if (i < N_NODES) {
        float d = g_deg[i];
        g_dinv[i] = d > 0.0f ? rsqrtf(d) : 0.0f;
    }
}

// ---------------- CSR bucket allocation: block scan + 1 global atomic -------
__global__ void __launch_bounds__(256) k_alloc() {
    __shared__ int sc[256];
    __shared__ int sbase;
    int tid = threadIdx.x;
    int i = blockIdx.x * 256 + tid;
    int v = (i < N_NODES) ? g_cnt[i] : 0;
    sc[tid] = v;
    __syncthreads();
#pragma unroll
    for (int off = 1; off < 256; off <<= 1) {
        int t = (tid >= off) ? sc[tid - off] : 0;
        __syncthreads();
        sc[tid] += t;
        __syncthreads();
    }
    if (tid == 255) sbase = atomicAdd(&g_total, sc[255]);
    __syncthreads();
    if (i < N_NODES) {
        int base = sbase + sc[tid] - v;   // exclusive within block
        g_off[i] = base;
        g_cur[i] = base;
    }
}

__global__ void k_fill(const int* __restrict__ row, const int* __restrict__ col,
                       const float* __restrict__ w) {
    int e = blockIdx.x * blockDim.x + threadIdx.x;
    if (e >= N_EDGES) return;
    int c = col[e];
    int pos = atomicAdd(&g_cur[c], 1);
    g_src[pos] = row[e];
    g_we[pos] = w[e];
}

// ---------------- GEMM1: double-buffered 8x8 register-tiled SGEMM ----------
// C[100000,128] = x[100000,256] @ W1[256,128]; BM=64 BN=128 BK=16, 128 thr.
// Epilogue: g_h1 = dinv*C.
__global__ void __launch_bounds__(128) k_gemm1(const float* __restrict__ x,
                                               const float* __restrict__ W) {
    __shared__ float As[2][16][64];    // [buf][k][m]
    __shared__ float Bs[2][16][128];   // [buf][k][n]
    int tid = threadIdx.x;
    int tx = tid & 15;   // n: cols tx*8..+8
    int ty = tid >> 4;   // m: rows ty*8..+8
    int row0 = blockIdx.x * 64;

    int ar = tid >> 1;          // A row within tile 0..63
    int ak = (tid & 1) * 8;     // A k offset 0 or 8
    int grow = row0 + ar;
    bool aok = grow < N_NODES;
    const float* asrc = x + (size_t)grow * IN_DIM + ak;

    const float4 z4 = make_float4(0.f, 0.f, 0.f, 0.f);
    float4 ra0 = aok ? *(const float4*)(asrc)     : z4;
    float4 ra1 = aok ? *(const float4*)(asrc + 4) : z4;
    // B cp.async indices (fixed per thread)
    int bidx0 = tid;
#pragma unroll
    for (int j = 0; j < 4; j++) {
        int idx = bidx0 + j * 128;
        int br = idx >> 5, bc = (idx & 31) * 4;
        cp_async16(&Bs[0][br][bc], W + (size_t)br * HID + bc);
    }
    CP_COMMIT();
    // stage A tile 0
    As[0][ak + 0][ar] = ra0.x; As[0][ak + 1][ar] = ra0.y;
    As[0][ak + 2][ar] = ra0.z; As[0][ak + 3][ar] = ra0.w;
    As[0][ak + 4][ar] = ra1.x; As[0][ak + 5][ar] = ra1.y;
    As[0][ak + 6][ar] = ra1.z; As[0][ak + 7][ar] = ra1.w;
    CP_WAIT0();
    __syncthreads();

    float acc[8][8];
#pragma unroll
    for (int i = 0; i < 8; i++)
#pragma unroll
        for (int j = 0; j < 8; j++) acc[i][j] = 0.0f;

#pragma unroll 1
    for (int t = 0; t < 16; t++) {
        int cur = t & 1, nxt = cur ^ 1;
        if (t < 15) {
            const float* an = asrc + (t + 1) * 16;
            ra0 = aok ? *(const float4*)(an)     : z4;
            ra1 = aok ? *(const float4*)(an + 4) : z4;
#pragma unroll
            for (int j = 0; j < 4; j++) {
                int idx = bidx0 + j * 128;
                int br = idx >> 5, bc = (idx & 31) * 4;
                cp_async16(&Bs[nxt][br][bc], W + (size_t)((t + 1) * 16 + br) * HID + bc);
            }
            CP_COMMIT();
        }
#pragma unroll
        for (int kk = 0; kk < 16; kk++) {
            float4 a0 = *(float4*)&As[cur][kk][ty * 8];
            float4 a1 = *(float4*)&As[cur][kk][ty * 8 + 4];
            float4 b0 = *(float4*)&Bs[cur][kk][tx * 8];
            float4 b1 = *(float4*)&Bs[cur][kk][tx * 8 + 4];
            float am[8] = {a0.x, a0.y, a0.z, a0.w, a1.x, a1.y, a1.z, a1.w};
            float bn[8] = {b0.x, b0.y, b0.z, b0.w, b1.x, b1.y, b1.z, b1.w};
#pragma unroll
            for (int i = 0; i < 8; i++)
#pragma unroll
                for (int j = 0; j < 8; j++)
                    acc[i][j] = fmaf(am[i], bn[j], acc[i][j]);
        }
        if (t < 15) {
            As[nxt][ak + 0][ar] = ra0.x; As[nxt][ak + 1][ar] = ra0.y;
            As[nxt][ak + 2][ar] = ra0.z; As[nxt][ak + 3][ar] = ra0.w;
            As[nxt][ak + 4][ar] = ra1.x; As[nxt][ak + 5][ar] = ra1.y;
            As[nxt][ak + 6][ar] = ra1.z; As[nxt][ak + 7][ar] = ra1.w;
            CP_WAIT0();
            __syncthreads();
        }
    }

#pragma unroll
    for (int i = 0; i < 8; i++) {
        int gr = row0 + ty * 8 + i;
        if (gr >= N_NODES) break;
        float s = g_dinv[gr];
        float* hp = g_h1 + (size_t)gr * HID + tx * 8;
        *(float4*)(hp)     = make_float4(s * acc[i][0], s * acc[i][1], s * acc[i][2], s * acc[i][3]);
        *(float4*)(hp + 4) = make_float4(s * acc[i][4], s * acc[i][5], s * acc[i][6], s * acc[i][7]);
    }
}

// ---------------- layer-1 aggregation: warp per target node, 128 dims -------
// a1[c] = dinv[c] * ( h1[c] + sum_e w_e * h1[src_e] )   (h1 carries dinv[src])
__global__ void k_agg1() {
    int gw = (blockIdx.x * blockDim.x + threadIdx.x) >> 5;
    if (gw >= N_NODES) return;
    int lane = threadIdx.x & 31;
    const float4* hv = (const float4*)g_h1;

    float4 acc0 = hv[(size_t)gw * 32 + lane];  // self term
    float4 acc1 = make_float4(0.f, 0.f, 0.f, 0.f);

    int beg = g_off[gw];
    int end = beg + g_cnt[gw];
    int e = beg;
    for (; e + 2 <= end; e += 2) {
        int s0 = g_src[e], s1 = g_src[e + 1];
        float w0 = g_we[e], w1 = g_we[e + 1];
        float4 v0 = hv[(size_t)s0 * 32 + lane];
        float4 v1 = hv[(size_t)s1 * 32 + lane];
        acc0.x = fmaf(w0, v0.x, acc0.x); acc0.y = fmaf(w0, v0.y, acc0.y);
        acc0.z = fmaf(w0, v0.z, acc0.z); acc0.w = fmaf(w0, v0.w, acc0.w);
        acc1.x = fmaf(w1, v1.x, acc1.x); acc1.y = fmaf(w1, v1.y, acc1.y);
        acc1.z = fmaf(w1, v1.z, acc1.z); acc1.w = fmaf(w1, v1.w, acc1.w);
    }
    if (e < end) {
        int s0 = g_src[e];
        float w0 = g_we[e];
        float4 v0 = hv[(size_t)s0 * 32 + lane];
        acc0.x = fmaf(w0, v0.x, acc0.x); acc0.y = fmaf(w0, v0.y, acc0.y);
        acc0.z = fmaf(w0, v0.z, acc0.z); acc0.w = fmaf(w0, v0.w, acc0.w);
    }
    float s = g_dinv[gw];
    float4 r = make_float4(s * (acc0.x + acc1.x), s * (acc0.y + acc1.y),
                           s * (acc0.z + acc1.z), s * (acc0.w + acc1.w));
    ((float4*)g_a1)[(size_t)gw * 32 + lane] = r;
}

// ---------------- GEMM2: C = relu(a1+b1) @ W2, h2 = dinv*C ------------------
// BM=64 BN=64 BK=32, 128 threads, thread tile 4x8.
__global__ void __launch_bounds__(128) k_gemm2(const float* __restrict__ W2,
                                               const float* __restrict__ b1) {
    __shared__ float As[32][64];   // [k][m]
    __shared__ float Bs[32][64];   // [k][n]
    __shared__ float b1s[HID];
    int tid = threadIdx.x;
    int tx = tid & 7;    // n: cols tx*8
    int ty = tid >> 3;   // m: rows ty*4 (0..15)
    int row0 = blockIdx.x * 64;

    if (tid < HID) b1s[tid] = b1[tid];
    __syncthreads();

    float acc[4][8];
#pragma unroll
    for (int i = 0; i < 4; i++)
#pragma unroll
        for (int j = 0; j < 8; j++) acc[i][j] = 0.0f;

    for (int kt = 0; kt < HID; kt += 32) {
        {
            int ar = tid >> 1;
            int grow = row0 + ar;
            const float* src = g_a1 + (size_t)grow * HID + kt;
#pragma unroll
            for (int j = 0; j < 4; j++) {
                int f4 = (tid & 1) * 4 + j;
                int kk = f4 * 4;
                float4 v = make_float4(0.f, 0.f, 0.f, 0.f);
                if (grow < N_NODES) {
                    v = *(const float4*)(src + kk);
                    v.x = fmaxf(v.x + b1s[kt + kk + 0], 0.f);
                    v.y = fmaxf(v.y + b1s[kt + kk + 1], 0.f);
                    v.z = fmaxf(v.z + b1s[kt + kk + 2], 0.f);
                    v.w = fmaxf(v.w + b1s[kt + kk + 3], 0.f);
                }
                As[kk + 0][ar] = v.x;
                As[kk + 1][ar] = v.y;
                As[kk + 2][ar] = v.z;
                As[kk + 3][ar] = v.w;
            }
        }
#pragma unroll
        for (int j = 0; j < 4; j++) {
            int idx = tid + j * 128;
            int br = idx >> 4;
            int bc = (idx & 15) * 4;
            *(float4*)&Bs[br][bc] = *(const float4*)(W2 + (size_t)(kt + br) * OUTD + bc);
        }
        __syncthreads();

#pragma unroll
        for (int kk = 0; kk < 32; kk++) {
            float4 a = *(float4*)&As[kk][ty * 4];
            float4 b0 = *(float4*)&Bs[kk][tx * 8];
            float4 b1v = *(float4*)&Bs[kk][tx * 8 + 4];
            float am[4] = {a.x, a.y, a.z, a.w};
            float bn[8] = {b0.x, b0.y, b0.z, b0.w, b1v.x, b1v.y, b1v.z, b1v.w};
#pragma unroll
            for (int i = 0; i < 4; i++)
#pragma unroll
                for (int j = 0; j < 8; j++)
                    acc[i][j] = fmaf(am[i], bn[j], acc[i][j]);
        }
        __syncthreads();
    }

#pragma unroll
    for (int i = 0; i < 4; i++) {
        int grow = row0 + ty * 4 + i;
        if (grow >= N_NODES) break;
        float s = g_dinv[grow];
        float* hp = g_h2 + (size_t)grow * OUTD + tx * 8;
        *(float4*)(hp)     = make_float4(s * acc[i][0], s * acc[i][1], s * acc[i][2], s * acc[i][3]);
        *(float4*)(hp + 4) = make_float4(s * acc[i][4], s * acc[i][5], s * acc[i][6], s * acc[i][7]);
    }
}

// ---------------- layer-2 aggregation: warp per node, 64 dims ---------------
// out[c] = dinv[c] * ( h2[c] + sum_e w_e * h2[src_e] ) + b2
__global__ void k_agg2(const float* __restrict__ b2, float* __restrict__ out) {
    int gw = (blockIdx.x * blockDim.x + threadIdx.x) >> 5;
    if (gw >= N_NODES) return;
    int lane = threadIdx.x & 31;
    const float2* hv = (const float2*)g_h2;

    float2 acc0 = hv[(size_t)gw * 32 + lane];  // self term
    float2 acc1 = make_float2(0.f, 0.f);

    int beg = g_off[gw];
    int end = beg + g_cnt[gw];
    int e = beg;
    for (; e + 2 <= end; e += 2) {
        int s0 = g_src[e], s1 = g_src[e + 1];
        float w0 = g_we[e], w1 = g_we[e + 1];
        float2 v0 = hv[(size_t)s0 * 32 + lane];
        float2 v1 = hv[(size_t)s1 * 32 + lane];
        acc0.x = fmaf(w0, v0.x, acc0.x); acc0.y = fmaf(w0, v0.y, acc0.y);
        acc1.x = fmaf(w1, v1.x, acc1.x); acc1.y = fmaf(w1, v1.y, acc1.y);
    }
    if (e < end) {
        int s0 = g_src[e];
        float w0 = g_we[e];
        float2 v0 = hv[(size_t)s0 * 32 + lane];
        acc0.x = fmaf(w0, v0.x, acc0.x); acc0.y = fmaf(w0, v0.y, acc0.y);
    }
    float s = g_dinv[gw];
    float2 bb = ((const float2*)b2)[lane];
    float2 r = make_float2(fmaf(s, acc0.x + acc1.x, bb.x),
                           fmaf(s, acc0.y + acc1.y, bb.y));
    ((float2*)out)[(size_t)gw * 32 + lane] = r;
}

// ---------------- launch ----------------
extern "C" void kernel_launch(void* const* d_in, const int* in_sizes, int n_in,
                              void* d_out, int out_size) {
    const float* x  = (const float*)d_in[0];
    const int*   ei = (const int*)d_in[1];   // int32 (JAX downgrades int64)
    const float* ew = (const float*)d_in[2];
    const float* W1 = (const float*)d_in[3];
    const float* b1 = (const float*)d_in[4];
    const float* W2 = (const float*)d_in[5];
    const float* b2 = (const float*)d_in[6];
    float*       out = (float*)d_out;

    const int* row = ei;            // edge_index[0]
    const int* col = ei + N_EDGES;  // edge_index[1]

    k_init<<<(N_NODES + 255) / 256, 256>>>();
    k_hist<<<(N_EDGES + 255) / 256, 256>>>(col, ew);
    k_dinv<<<(N_NODES + 255) / 256, 256>>>();
    k_alloc<<<(N_NODES + 255) / 256, 256>>>();
    k_fill<<<(N_EDGES + 255) / 256, 256>>>(row, col, ew);

    k_gemm1<<<(N_NODES + 63) / 64, 128>>>(x, W1);
    k_agg1<<<(N_NODES * 32 + 255) / 256, 256>>>();

    k_gemm2<<<(N_NODES + 63) / 64, 128>>>(W2, b1);
    k_agg2<<<(N_NODES * 32 + 255) / 256, 256>>>(b2, out);
}

// round 6
// speedup vs baseline: 3.0523x; 1.1747x over previous
#include <cuda_runtime.h>
#include <cuda_bf16.h>
#include <cstdint>

#define N_NODES 100000
#define N_EDGES 1600000
#define IN_DIM 256
#define HID 128
#define OUTD 64

// ---------------- scratch (device globals; no allocs allowed) ----------------
__device__ float g_deg[N_NODES];
__device__ float g_dinv[N_NODES];
__device__ int   g_cnt[N_NODES];
__device__ int   g_off[N_NODES];
__device__ int   g_cur[N_NODES];
__device__ int   g_total;
__device__ int   g_src[N_EDGES];
__device__ float g_we[N_EDGES];
__device__ __nv_bfloat16 g_B1hi[HID * IN_DIM];  // W1 split, [n][k] layout
__device__ __nv_bfloat16 g_B1lo[HID * IN_DIM];
__device__ float g_h1[(size_t)N_NODES * HID];   // dinv * (x @ W1)
__device__ float g_a1[(size_t)N_NODES * HID];   // aggregated layer-1
__device__ float g_h2[(size_t)N_NODES * OUTD];  // dinv * (relu(a1+b1) @ W2)

__device__ __forceinline__ uint32_t smem_u32(const void* p) {
    uint32_t a;
    asm("{ .reg .u64 t; cvta.to.shared.u64 t, %1; cvt.u32.u64 %0, t; }" : "=r"(a) : "l"(p));
    return a;
}
__device__ __forceinline__ void ldm4(uint32_t* r, uint32_t addr) {
    asm volatile("ldmatrix.sync.aligned.m8n8.x4.shared.b16 {%0,%1,%2,%3}, [%4];"
                 : "=r"(r[0]), "=r"(r[1]), "=r"(r[2]), "=r"(r[3]) : "r"(addr));
}
__device__ __forceinline__ void mma_bf16(float* d, const uint32_t* a, const uint32_t* b) {
    asm volatile(
        "mma.sync.aligned.m16n8k16.row.col.f32.bf16.bf16.f32 "
        "{%0,%1,%2,%3}, {%4,%5,%6,%7}, {%8,%9}, {%0,%1,%2,%3};"
        : "+f"(d[0]), "+f"(d[1]), "+f"(d[2]), "+f"(d[3])
        : "r"(a[0]), "r"(a[1]), "r"(a[2]), "r"(a[3]), "r"(b[0]), "r"(b[1]));
}

// ---------------- init / degree / normalization ----------------
__global__ void k_init() {
    int i = blockIdx.x * blockDim.x + threadIdx.x;
    if (i < N_NODES) { g_deg[i] = 1.0f; g_cnt[i] = 0; }
    if (i == 0) g_total = 0;
}

__global__ void k_hist(const int* __restrict__ col, const float* __restrict__ w) {
    int e = blockIdx.x * blockDim.x + threadIdx.x;
    if (e < N_EDGES) {
        int c = col[e];
        atomicAdd(&g_deg[c], w[e]);
        atomicAdd(&g_cnt[c], 1);
    }
}

__global__ void k_dinv() {
    int i = blockIdx.x * blockDim.x + threadIdx.x;
    if (i < N_NODES) {
        float d = g_deg[i];
        g_dinv[i] = d > 0.0f ? rsqrtf(d) : 0.0f;
    }
}

// ---------------- W1 -> bf16 hi/lo split, transposed to [n][k] ----------------
__global__ void k_convW1(const float* __restrict__ W1) {
    int i = blockIdx.x * blockDim.x + threadIdx.x;  // i = n*256 + k
    if (i >= HID * IN_DIM) return;
    int n = i >> 8, k = i & 255;
    float w = W1[(size_t)k * HID + n];
    __nv_bfloat16 h = __float2bfloat16(w);
    g_B1hi[i] = h;
    g_B1lo[i] = __float2bfloat16(w - __bfloat162float(h));
}

// ---------------- CSR bucket allocation ----------------
__global__ void __launch_bounds__(256) k_alloc() {
    __shared__ int sc[256];
    __shared__ int sbase;
    int tid = threadIdx.x;
    int i = blockIdx.x * 256 + tid;
    int v = (i < N_NODES) ? g_cnt[i] : 0;
    sc[tid] = v;
    __syncthreads();
#pragma unroll
    for (int off = 1; off < 256; off <<= 1) {
        int t = (tid >= off) ? sc[tid - off] : 0;
        __syncthreads();
        sc[tid] += t;
        __syncthreads();
    }
    if (tid == 255) sbase = atomicAdd(&g_total, sc[255]);
    __syncthreads();
    if (i < N_NODES) {
        int base = sbase + sc[tid] - v;
        g_off[i] = base;
        g_cur[i] = base;
    }
}

__global__ void k_fill(const int* __restrict__ row, const int* __restrict__ col,
                       const float* __restrict__ w) {
    int e = blockIdx.x * blockDim.x + threadIdx.x;
    if (e >= N_EDGES) return;
    int c = col[e];
    int pos = atomicAdd(&g_cur[c], 1);
    g_src[pos] = row[e];
    g_we[pos] = w[e];
}

// ---------------- GEMM1 via mma.sync bf16 3-term split ----------------
// C[100000,128] = x[100000,256] @ W1; BM=128 BN=128 BK=32, 256 thr (8 warps 4x2).
// smem tiles padded to 40 bf16/row (80B): ldmatrix conflict-free (stride 5 in 16B units).
#define APAD 40
__global__ void __launch_bounds__(256) k_gemm1_mma(const float* __restrict__ x) {
    __shared__ __align__(16) __nv_bfloat16 sAhi[128 * APAD];
    __shared__ __align__(16) __nv_bfloat16 sAlo[128 * APAD];
    __shared__ __align__(16) __nv_bfloat16 sBhi[128 * APAD];
    __shared__ __align__(16) __nv_bfloat16 sBlo[128 * APAD];

    int tid = threadIdx.x;
    int lane = tid & 31;
    int wid = tid >> 5;
    int wm = (wid & 3) * 32;    // warp rows 32
    int wn = (wid >> 2) * 64;   // warp cols 64
    int row0 = blockIdx.x * 128;

    uint32_t aHiB = smem_u32(sAhi);
    uint32_t aLoB = smem_u32(sAlo);
    uint32_t bHiB = smem_u32(sBhi);
    uint32_t bLoB = smem_u32(sBlo);

    // per-lane ldmatrix address offsets
    int within = lane & 7, sub = lane >> 3;
    int aRow = within + (sub & 1) * 8;     // row offset within m16
    int aK   = (sub >> 1) * 8;             // k offset within k16
    int bN   = within + (sub >> 1) * 8;    // n offset within n16 (pair of n8 frags)
    int bK   = (sub & 1) * 8;

    float acc[2][8][4];
#pragma unroll
    for (int mf = 0; mf < 2; mf++)
#pragma unroll
        for (int nf = 0; nf < 8; nf++)
#pragma unroll
            for (int q = 0; q < 4; q++) acc[mf][nf][q] = 0.0f;

    // A-fill constants
    int fr = tid >> 1;            // 0..127
    int fhalf = tid & 1;          // k half (16 each)
    int grow = row0 + fr;
    bool aok = grow < N_NODES;
    const float* asrc = x + (size_t)grow * IN_DIM + fhalf * 16;

    for (int kt = 0; kt < IN_DIM; kt += 32) {
        // ---- A tile: 128 x 32 f32 -> bf16 hi/lo ----
#pragma unroll
        for (int j = 0; j < 4; j++) {
            float4 v = make_float4(0.f, 0.f, 0.f, 0.f);
            if (aok) v = *(const float4*)(asrc + kt + j * 4);
            __nv_bfloat162 h01 = __floats2bfloat162_rn(v.x, v.y);
            __nv_bfloat162 h23 = __floats2bfloat162_rn(v.z, v.w);
            float2 f01 = __bfloat1622float2(h01);
            float2 f23 = __bfloat1622float2(h23);
            __nv_bfloat162 l01 = __floats2bfloat162_rn(v.x - f01.x, v.y - f01.y);
            __nv_bfloat162 l23 = __floats2bfloat162_rn(v.z - f23.x, v.w - f23.y);
            int eoff = fr * APAD + fhalf * 16 + j * 4;
            *(__nv_bfloat162*)&sAhi[eoff]     = h01;
            *(__nv_bfloat162*)&sAhi[eoff + 2] = h23;
            *(__nv_bfloat162*)&sAlo[eoff]     = l01;
            *(__nv_bfloat162*)&sAlo[eoff + 2] = l23;
        }
        // ---- B tiles: 128 n x 32 k bf16, 16B chunks ----
#pragma unroll
        for (int j = 0; j < 2; j++) {
            int i = tid + j * 256;          // 512 chunks
            int n = i >> 2, c8 = i & 3;
            const __nv_bfloat16* sh = g_B1hi + (size_t)n * IN_DIM + kt + c8 * 8;
            const __nv_bfloat16* sl = g_B1lo + (size_t)n * IN_DIM + kt + c8 * 8;
            *(uint4*)&sBhi[n * APAD + c8 * 8] = *(const uint4*)sh;
            *(uint4*)&sBlo[n * APAD + c8 * 8] = *(const uint4*)sl;
        }
        __syncthreads();

#pragma unroll
        for (int kf = 0; kf < 2; kf++) {
            int kk = kf * 16;
            uint32_t ahi[2][4], alo[2][4];
#pragma unroll
            for (int mf = 0; mf < 2; mf++) {
                uint32_t off = (uint32_t)((wm + mf * 16 + aRow) * APAD + kk + aK) * 2;
                ldm4(ahi[mf], aHiB + off);
                ldm4(alo[mf], aLoB + off);
            }
#pragma unroll
            for (int np = 0; np < 4; np++) {
                uint32_t bh[4], bl[4];
                uint32_t off = (uint32_t)((wn + np * 16 + bN) * APAD + kk + bK) * 2;
                ldm4(bh, bHiB + off);
                ldm4(bl, bLoB + off);
#pragma unroll
                for (int s = 0; s < 2; s++) {
                    int nf = np * 2 + s;
#pragma unroll
                    for (int mf = 0; mf < 2; mf++) {
                        mma_bf16(acc[mf][nf], ahi[mf], bh + s * 2);  // hi*hi
                        mma_bf16(acc[mf][nf], ahi[mf], bl + s * 2);  // hi*lo
                        mma_bf16(acc[mf][nf], alo[mf], bh + s * 2);  // lo*hi
                    }
                }
            }
        }
        __syncthreads();
    }

    // ---- epilogue: g_h1 = dinv * C ----
    int g = lane >> 2, t4 = lane & 3;
#pragma unroll
    for (int mf = 0; mf < 2; mf++) {
        int r0 = row0 + wm + mf * 16 + g;
        int r1 = r0 + 8;
        float s0 = (r0 < N_NODES) ? g_dinv[r0] : 0.0f;
        float s1 = (r1 < N_NODES) ? g_dinv[r1] : 0.0f;
#pragma unroll
        for (int nf = 0; nf < 8; nf++) {
            int cb = wn + nf * 8 + t4 * 2;
            if (r0 < N_NODES)
                *(float2*)(g_h1 + (size_t)r0 * HID + cb) =
                    make_float2(s0 * acc[mf][nf][0], s0 * acc[mf][nf][1]);
            if (r1 < N_NODES)
                *(float2*)(g_h1 + (size_t)r1 * HID + cb) =
                    make_float2(s1 * acc[mf][nf][2], s1 * acc[mf][nf][3]);
        }
    }
}

// ---------------- layer-1 aggregation: warp per target node ----------------
__global__ void k_agg1() {
    int gw = (blockIdx.x * blockDim.x + threadIdx.x) >> 5;
    if (gw >= N_NODES) return;
    int lane = threadIdx.x & 31;
    const float4* hv = (const float4*)g_h1;

    float4 acc0 = hv[(size_t)gw * 32 + lane];  // self term
    float4 acc1 = make_float4(0.f, 0.f, 0.f, 0.f);

    int beg = g_off[gw];
    int end = beg + g_cnt[gw];
    int e = beg;
    for (; e + 2 <= end; e += 2) {
        int s0 = g_src[e], s1 = g_src[e + 1];
        float w0 = g_we[e], w1 = g_we[e + 1];
        float4 v0 = hv[(size_t)s0 * 32 + lane];
        float4 v1 = hv[(size_t)s1 * 32 + lane];
        acc0.x = fmaf(w0, v0.x, acc0.x); acc0.y = fmaf(w0, v0.y, acc0.y);
        acc0.z = fmaf(w0, v0.z, acc0.z); acc0.w = fmaf(w0, v0.w, acc0.w);
        acc1.x = fmaf(w1, v1.x, acc1.x); acc1.y = fmaf(w1, v1.y, acc1.y);
        acc1.z = fmaf(w1, v1.z, acc1.z); acc1.w = fmaf(w1, v1.w, acc1.w);
    }
    if (e < end) {
        int s0 = g_src[e];
        float w0 = g_we[e];
        float4 v0 = hv[(size_t)s0 * 32 + lane];
        acc0.x = fmaf(w0, v0.x, acc0.x); acc0.y = fmaf(w0, v0.y, acc0.y);
        acc0.z = fmaf(w0, v0.z, acc0.z); acc0.w = fmaf(w0, v0.w, acc0.w);
    }
    float s = g_dinv[gw];
    float4 r = make_float4(s * (acc0.x + acc1.x), s * (acc0.y + acc1.y),
                           s * (acc0.z + acc1.z), s * (acc0.w + acc1.w));
    ((float4*)g_a1)[(size_t)gw * 32 + lane] = r;
}

// ---------------- GEMM2: C = relu(a1+b1) @ W2, h2 = dinv*C ------------------
__global__ void __launch_bounds__(128) k_gemm2(const float* __restrict__ W2,
                                               const float* __restrict__ b1) {
    __shared__ float As[32][64];
    __shared__ float Bs[32][64];
    __shared__ float b1s[HID];
    int tid = threadIdx.x;
    int tx = tid & 7;
    int ty = tid >> 3;
    int row0 = blockIdx.x * 64;

    if (tid < HID) b1s[tid] = b1[tid];
    __syncthreads();

    float acc[4][8];
#pragma unroll
    for (int i = 0; i < 4; i++)
#pragma unroll
        for (int j = 0; j < 8; j++) acc[i][j] = 0.0f;

    for (int kt = 0; kt < HID; kt += 32) {
        {
            int ar = tid >> 1;
            int grow = row0 + ar;
            const float* src = g_a1 + (size_t)grow * HID + kt;
#pragma unroll
            for (int j = 0; j < 4; j++) {
                int f4 = (tid & 1) * 4 + j;
                int kk = f4 * 4;
                float4 v = make_float4(0.f, 0.f, 0.f, 0.f);
                if (grow < N_NODES) {
                    v = *(const float4*)(src + kk);
                    v.x = fmaxf(v.x + b1s[kt + kk + 0], 0.f);
                    v.y = fmaxf(v.y + b1s[kt + kk + 1], 0.f);
                    v.z = fmaxf(v.z + b1s[kt + kk + 2], 0.f);
                    v.w = fmaxf(v.w + b1s[kt + kk + 3], 0.f);
                }
                As[kk + 0][ar] = v.x;
                As[kk + 1][ar] = v.y;
                As[kk + 2][ar] = v.z;
                As[kk + 3][ar] = v.w;
            }
        }
#pragma unroll
        for (int j = 0; j < 4; j++) {
            int idx = tid + j * 128;
            int br = idx >> 4;
            int bc = (idx & 15) * 4;
            *(float4*)&Bs[br][bc] = *(const float4*)(W2 + (size_t)(kt + br) * OUTD + bc);
        }
        __syncthreads();

#pragma unroll
        for (int kk = 0; kk < 32; kk++) {
            float4 a = *(float4*)&As[kk][ty * 4];
            float4 b0 = *(float4*)&Bs[kk][tx * 8];
            float4 b1v = *(float4*)&Bs[kk][tx * 8 + 4];
            float am[4] = {a.x, a.y, a.z, a.w};
            float bn[8] = {b0.x, b0.y, b0.z, b0.w, b1v.x, b1v.y, b1v.z, b1v.w};
#pragma unroll
            for (int i = 0; i < 4; i++)
#pragma unroll
                for (int j = 0; j < 8; j++)
                    acc[i][j] = fmaf(am[i], bn[j], acc[i][j]);
        }
        __syncthreads();
    }

#pragma unroll
    for (int i = 0; i < 4; i++) {
        int grow = row0 + ty * 4 + i;
        if (grow >= N_NODES) break;
        float s = g_dinv[grow];
        float* hp = g_h2 + (size_t)grow * OUTD + tx * 8;
        *(float4*)(hp)     = make_float4(s * acc[i][0], s * acc[i][1], s * acc[i][2], s * acc[i][3]);
        *(float4*)(hp + 4) = make_float4(s * acc[i][4], s * acc[i][5], s * acc[i][6], s * acc[i][7]);
    }
}

// ---------------- layer-2 aggregation: warp per node ----------------
__global__ void k_agg2(const float* __restrict__ b2, float* __restrict__ out) {
    int gw = (blockIdx.x * blockDim.x + threadIdx.x) >> 5;
    if (gw >= N_NODES) return;
    int lane = threadIdx.x & 31;
    const float2* hv = (const float2*)g_h2;

    float2 acc0 = hv[(size_t)gw * 32 + lane];
    float2 acc1 = make_float2(0.f, 0.f);

    int beg = g_off[gw];
    int end = beg + g_cnt[gw];
    int e = beg;
    for (; e + 2 <= end; e += 2) {
        int s0 = g_src[e], s1 = g_src[e + 1];
        float w0 = g_we[e], w1 = g_we[e + 1];
        float2 v0 = hv[(size_t)s0 * 32 + lane];
        float2 v1 = hv[(size_t)s1 * 32 + lane];
        acc0.x = fmaf(w0, v0.x, acc0.x); acc0.y = fmaf(w0, v0.y, acc0.y);
        acc1.x = fmaf(w1, v1.x, acc1.x); acc1.y = fmaf(w1, v1.y, acc1.y);
    }
    if (e < end) {
        int s0 = g_src[e];
        float w0 = g_we[e];
        float2 v0 = hv[(size_t)s0 * 32 + lane];
        acc0.x = fmaf(w0, v0.x, acc0.x); acc0.y = fmaf(w0, v0.y, acc0.y);
    }
    float s = g_dinv[gw];
    float2 bb = ((const float2*)b2)[lane];
    float2 r = make_float2(fmaf(s, acc0.x + acc1.x, bb.x),
                           fmaf(s, acc0.y + acc1.y, bb.y));
    ((float2*)out)[(size_t)gw * 32 + lane] = r;
}

// ---------------- launch ----------------
extern "C" void kernel_launch(void* const* d_in, const int* in_sizes, int n_in,
                              void* d_out, int out_size) {
    const float* x  = (const float*)d_in[0];
    const int*   ei = (const int*)d_in[1];   // int32 (JAX downgrades int64)
    const float* ew = (const float*)d_in[2];
    const float* W1 = (const float*)d_in[3];
    const float* b1 = (const float*)d_in[4];
    const float* W2 = (const float*)d_in[5];
    const float* b2 = (const float*)d_in[6];
    float*       out = (float*)d_out;

    const int* row = ei;
    const int* col = ei + N_EDGES;

    k_init<<<(N_NODES + 255) / 256, 256>>>();
    k_hist<<<(N_EDGES + 255) / 256, 256>>>(col, ew);
    k_dinv<<<(N_NODES + 255) / 256, 256>>>();
    k_alloc<<<(N_NODES + 255) / 256, 256>>>();
    k_fill<<<(N_EDGES + 255) / 256, 256>>>(row, col, ew);
    k_convW1<<<(HID * IN_DIM + 255) / 256, 256>>>(W1);

    k_gemm1_mma<<<(N_NODES + 127) / 128, 256>>>(x);
    k_agg1<<<(N_NODES * 32 + 255) / 256, 256>>>();

    k_gemm2<<<(N_NODES + 63) / 64, 128>>>(W2, b1);
    k_agg2<<<(N_NODES * 32 + 255) / 256, 256>>>(b2, out);
}

// round 7
// speedup vs baseline: 3.7682x; 1.2345x over previous
#include <cuda_runtime.h>
#include <cuda_bf16.h>
#include <cuda_fp16.h>
#include <cstdint>

#define N_NODES 100000
#define N_EDGES 1600000
#define IN_DIM 256
#define HID 128
#define OUTD 64

// ---------------- scratch (device globals; no allocs allowed) ----------------
__device__ float g_deg[N_NODES];
__device__ float g_dinv[N_NODES];
__device__ int   g_cnt[N_NODES];
__device__ int   g_off[N_NODES];
__device__ int   g_cur[N_NODES];
__device__ int   g_total;
__device__ int   g_src[N_EDGES];
__device__ float g_we[N_EDGES];
__device__ __nv_bfloat16 g_B1hi[HID * IN_DIM];  // W1 split, [n][k]
__device__ __nv_bfloat16 g_B1lo[HID * IN_DIM];
__device__ __nv_bfloat16 g_B2hi[OUTD * HID];    // W2 split, [n][k]
__device__ __nv_bfloat16 g_B2lo[OUTD * HID];
__device__ __half g_h1[(size_t)N_NODES * HID];  // fp16: dinv * (x @ W1)
__device__ float  g_a1[(size_t)N_NODES * HID];  // f32 aggregated layer-1
__device__ __half g_h2[(size_t)N_NODES * OUTD]; // fp16: dinv * (relu(a1+b1) @ W2)

__device__ __forceinline__ uint32_t smem_u32(const void* p) {
    uint32_t a;
    asm("{ .reg .u64 t; cvta.to.shared.u64 t, %1; cvt.u32.u64 %0, t; }" : "=r"(a) : "l"(p));
    return a;
}
__device__ __forceinline__ void ldm4(uint32_t* r, uint32_t addr) {
    asm volatile("ldmatrix.sync.aligned.m8n8.x4.shared.b16 {%0,%1,%2,%3}, [%4];"
                 : "=r"(r[0]), "=r"(r[1]), "=r"(r[2]), "=r"(r[3]) : "r"(addr));
}
__device__ __forceinline__ void mma_bf16(float* d, const uint32_t* a, const uint32_t* b) {
    asm volatile(
        "mma.sync.aligned.m16n8k16.row.col.f32.bf16.bf16.f32 "
        "{%0,%1,%2,%3}, {%4,%5,%6,%7}, {%8,%9}, {%0,%1,%2,%3};"
        : "+f"(d[0]), "+f"(d[1]), "+f"(d[2]), "+f"(d[3])
        : "r"(a[0]), "r"(a[1]), "r"(a[2]), "r"(a[3]), "r"(b[0]), "r"(b[1]));
}
__device__ __forceinline__ float4 ld_h4(const __half* p) {  // 4 fp16 -> 4 f32
    uint2 u = *(const uint2*)p;
    __half2 a = *(__half2*)&u.x, b = *(__half2*)&u.y;
    float2 fa = __half22float2(a), fb = __half22float2(b);
    return make_float4(fa.x, fa.y, fb.x, fb.y);
}

// ---------------- fused setup: deg/cnt init + W1/W2 bf16 hi-lo splits -------
__global__ void k_setup(const float* __restrict__ W1, const float* __restrict__ W2) {
    int i = blockIdx.x * blockDim.x + threadIdx.x;
    if (i < N_NODES) { g_deg[i] = 1.0f; g_cnt[i] = 0; }
    if (i == 0) g_total = 0;
    if (i < HID * IN_DIM) {               // W1: [k][n] -> [n][k] split
        int n = i >> 8, k = i & 255;
        float w = W1[(size_t)k * HID + n];
        __nv_bfloat16 h = __float2bfloat16(w);
        g_B1hi[i] = h;
        g_B1lo[i] = __float2bfloat16(w - __bfloat162float(h));
    }
    if (i < OUTD * HID) {                 // W2: [k][n] -> [n][k] split
        int n = i >> 7, k = i & 127;
        float w = W2[(size_t)k * OUTD + n];
        __nv_bfloat16 h = __float2bfloat16(w);
        g_B2hi[i] = h;
        g_B2lo[i] = __float2bfloat16(w - __bfloat162float(h));
    }
}

__global__ void k_hist(const int* __restrict__ col, const float* __restrict__ w) {
    int e = blockIdx.x * blockDim.x + threadIdx.x;
    if (e < N_EDGES) {
        int c = col[e];
        atomicAdd(&g_deg[c], w[e]);
        atomicAdd(&g_cnt[c], 1);
    }
}

__global__ void k_dinv() {
    int i = blockIdx.x * blockDim.x + threadIdx.x;
    if (i < N_NODES) {
        float d = g_deg[i];
        g_dinv[i] = d > 0.0f ? rsqrtf(d) : 0.0f;
    }
}

// ---------------- GEMM1 via mma.sync bf16 3-term split ----------------
// C[100000,128] = x[100000,256] @ W1; BM=128 BN=128 BK=32, 256 thr (8 warps 4x2).
#define APAD 40
__global__ void __launch_bounds__(256) k_gemm1_mma(const float* __restrict__ x) {
    __shared__ __align__(16) __nv_bfloat16 sAhi[128 * APAD];
    __shared__ __align__(16) __nv_bfloat16 sAlo[128 * APAD];
    __shared__ __align__(16) __nv_bfloat16 sBhi[128 * APAD];
    __shared__ __align__(16) __nv_bfloat16 sBlo[128 * APAD];

    int tid = threadIdx.x;
    int lane = tid & 31;
    int wid = tid >> 5;
    int wm = (wid & 3) * 32;
    int wn = (wid >> 2) * 64;
    int row0 = blockIdx.x * 128;

    uint32_t aHiB = smem_u32(sAhi);
    uint32_t aLoB = smem_u32(sAlo);
    uint32_t bHiB = smem_u32(sBhi);
    uint32_t bLoB = smem_u32(sBlo);

    int within = lane & 7, sub = lane >> 3;
    int aRow = within + (sub & 1) * 8;
    int aK   = (sub >> 1) * 8;
    int bN   = within + (sub >> 1) * 8;
    int bK   = (sub & 1) * 8;

    float acc[2][8][4];
#pragma unroll
    for (int mf = 0; mf < 2; mf++)
#pragma unroll
        for (int nf = 0; nf < 8; nf++)
#pragma unroll
            for (int q = 0; q < 4; q++) acc[mf][nf][q] = 0.0f;

    int fr = tid >> 1;
    int fhalf = tid & 1;
    int grow = row0 + fr;
    bool aok = grow < N_NODES;
    const float* asrc = x + (size_t)grow * IN_DIM + fhalf * 16;

    for (int kt = 0; kt < IN_DIM; kt += 32) {
#pragma unroll
        for (int j = 0; j < 4; j++) {
            float4 v = make_float4(0.f, 0.f, 0.f, 0.f);
            if (aok) v = *(const float4*)(asrc + kt + j * 4);
            __nv_bfloat162 h01 = __floats2bfloat162_rn(v.x, v.y);
            __nv_bfloat162 h23 = __floats2bfloat162_rn(v.z, v.w);
            float2 f01 = __bfloat1622float2(h01);
            float2 f23 = __bfloat1622float2(h23);
            __nv_bfloat162 l01 = __floats2bfloat162_rn(v.x - f01.x, v.y - f01.y);
            __nv_bfloat162 l23 = __floats2bfloat162_rn(v.z - f23.x, v.w - f23.y);
            int eoff = fr * APAD + fhalf * 16 + j * 4;
            *(__nv_bfloat162*)&sAhi[eoff]     = h01;
            *(__nv_bfloat162*)&sAhi[eoff + 2] = h23;
            *(__nv_bfloat162*)&sAlo[eoff]     = l01;
            *(__nv_bfloat162*)&sAlo[eoff + 2] = l23;
        }
#pragma unroll
        for (int j = 0; j < 2; j++) {
            int i = tid + j * 256;
            int n = i >> 2, c8 = i & 3;
            const __nv_bfloat16* sh = g_B1hi + (size_t)n * IN_DIM + kt + c8 * 8;
            const __nv_bfloat16* sl = g_B1lo + (size_t)n * IN_DIM + kt + c8 * 8;
            *(uint4*)&sBhi[n * APAD + c8 * 8] = *(const uint4*)sh;
            *(uint4*)&sBlo[n * APAD + c8 * 8] = *(const uint4*)sl;
        }
        __syncthreads();

#pragma unroll
        for (int kf = 0; kf < 2; kf++) {
            int kk = kf * 16;
            uint32_t ahi[2][4], alo[2][4];
#pragma unroll
            for (int mf = 0; mf < 2; mf++) {
                uint32_t off = (uint32_t)((wm + mf * 16 + aRow) * APAD + kk + aK) * 2;
                ldm4(ahi[mf], aHiB + off);
                ldm4(alo[mf], aLoB + off);
            }
#pragma unroll
            for (int np = 0; np < 4; np++) {
                uint32_t bh[4], bl[4];
                uint32_t off = (uint32_t)((wn + np * 16 + bN) * APAD + kk + bK) * 2;
                ldm4(bh, bHiB + off);
                ldm4(bl, bLoB + off);
#pragma unroll
                for (int s = 0; s < 2; s++) {
                    int nf = np * 2 + s;
#pragma unroll
                    for (int mf = 0; mf < 2; mf++) {
                        mma_bf16(acc[mf][nf], ahi[mf], bh + s * 2);
                        mma_bf16(acc[mf][nf], ahi[mf], bl + s * 2);
                        mma_bf16(acc[mf][nf], alo[mf], bh + s * 2);
                    }
                }
            }
        }
        __syncthreads();
    }

    // epilogue: g_h1 (fp16) = dinv * C
    int g = lane >> 2, t4 = lane & 3;
#pragma unroll
    for (int mf = 0; mf < 2; mf++) {
        int r0 = row0 + wm + mf * 16 + g;
        int r1 = r0 + 8;
        float s0 = (r0 < N_NODES) ? g_dinv[r0] : 0.0f;
        float s1 = (r1 < N_NODES) ? g_dinv[r1] : 0.0f;
#pragma unroll
        for (int nf = 0; nf < 8; nf++) {
            int cb = wn + nf * 8 + t4 * 2;
            if (r0 < N_NODES)
                *(__half2*)(g_h1 + (size_t)r0 * HID + cb) =
                    __floats2half2_rn(s0 * acc[mf][nf][0], s0 * acc[mf][nf][1]);
            if (r1 < N_NODES)
                *(__half2*)(g_h1 + (size_t)r1 * HID + cb) =
                    __floats2half2_rn(s1 * acc[mf][nf][2], s1 * acc[mf][nf][3]);
        }
    }
}

// ---------------- CSR bucket allocation ----------------
__global__ void __launch_bounds__(256) k_alloc() {
    __shared__ int sc[256];
    __shared__ int sbase;
    int tid = threadIdx.x;
    int i = blockIdx.x * 256 + tid;
    int v = (i < N_NODES) ? g_cnt[i] : 0;
    sc[tid] = v;
    __syncthreads();
#pragma unroll
    for (int off = 1; off < 256; off <<= 1) {
        int t = (tid >= off) ? sc[tid - off] : 0;
        __syncthreads();
        sc[tid] += t;
        __syncthreads();
    }
    if (tid == 255) sbase = atomicAdd(&g_total, sc[255]);
    __syncthreads();
    if (i < N_NODES) {
        int base = sbase + sc[tid] - v;
        g_off[i] = base;
        g_cur[i] = base;
    }
}

__global__ void k_fill(const int* __restrict__ row, const int* __restrict__ col,
                       const float* __restrict__ w) {
    int e = blockIdx.x * blockDim.x + threadIdx.x;
    if (e >= N_EDGES) return;
    int c = col[e];
    int pos = atomicAdd(&g_cur[c], 1);
    g_src[pos] = row[e];
    g_we[pos] = w[e];
}

// ---------------- layer-1 aggregation: warp per node, fp16 gathers ----------
__global__ void k_agg1() {
    int gw = (blockIdx.x * blockDim.x + threadIdx.x) >> 5;
    if (gw >= N_NODES) return;
    int lane = threadIdx.x & 31;
    const __half* hbase = g_h1;
    int doff = lane * 4;

    float4 acc0 = ld_h4(hbase + (size_t)gw * HID + doff);  // self
    float4 acc1 = make_float4(0.f, 0.f, 0.f, 0.f);

    int beg = g_off[gw];
    int end = beg + g_cnt[gw];
    int e = beg;
    for (; e + 2 <= end; e += 2) {
        int s0 = g_src[e], s1 = g_src[e + 1];
        float w0 = g_we[e], w1 = g_we[e + 1];
        float4 v0 = ld_h4(hbase + (size_t)s0 * HID + doff);
        float4 v1 = ld_h4(hbase + (size_t)s1 * HID + doff);
        acc0.x = fmaf(w0, v0.x, acc0.x); acc0.y = fmaf(w0, v0.y, acc0.y);
        acc0.z = fmaf(w0, v0.z, acc0.z); acc0.w = fmaf(w0, v0.w, acc0.w);
        acc1.x = fmaf(w1, v1.x, acc1.x); acc1.y = fmaf(w1, v1.y, acc1.y);
        acc1.z = fmaf(w1, v1.z, acc1.z); acc1.w = fmaf(w1, v1.w, acc1.w);
    }
    if (e < end) {
        int s0 = g_src[e];
        float w0 = g_we[e];
        float4 v0 = ld_h4(hbase + (size_t)s0 * HID + doff);
        acc0.x = fmaf(w0, v0.x, acc0.x); acc0.y = fmaf(w0, v0.y, acc0.y);
        acc0.z = fmaf(w0, v0.z, acc0.z); acc0.w = fmaf(w0, v0.w, acc0.w);
    }
    float s = g_dinv[gw];
    float4 r = make_float4(s * (acc0.x + acc1.x), s * (acc0.y + acc1.y),
                           s * (acc0.z + acc1.z), s * (acc0.w + acc1.w));
    *(float4*)(g_a1 + (size_t)gw * HID + doff) = r;
}

// ---------------- GEMM2 via mma.sync bf16 3-term split ----------------
// C[100000,64] = relu(a1+b1) @ W2; BM=128 BN=64 BK=32, 256 thr (8 warps 4x2).
__global__ void __launch_bounds__(256) k_gemm2_mma(const float* __restrict__ b1) {
    __shared__ __align__(16) __nv_bfloat16 sAhi[128 * APAD];
    __shared__ __align__(16) __nv_bfloat16 sAlo[128 * APAD];
    __shared__ __align__(16) __nv_bfloat16 sBhi[64 * APAD];
    __shared__ __align__(16) __nv_bfloat16 sBlo[64 * APAD];
    __shared__ float b1s[HID];

    int tid = threadIdx.x;
    int lane = tid & 31;
    int wid = tid >> 5;
    int wm = (wid & 3) * 32;
    int wn = (wid >> 2) * 32;
    int row0 = blockIdx.x * 128;

    if (tid < HID) b1s[tid] = b1[tid];
    __syncthreads();

    uint32_t aHiB = smem_u32(sAhi);
    uint32_t aLoB = smem_u32(sAlo);
    uint32_t bHiB = smem_u32(sBhi);
    uint32_t bLoB = smem_u32(sBlo);

    int within = lane & 7, sub = lane >> 3;
    int aRow = within + (sub & 1) * 8;
    int aK   = (sub >> 1) * 8;
    int bN   = within + (sub >> 1) * 8;
    int bK   = (sub & 1) * 8;

    float acc[2][4][4];
#pragma unroll
    for (int mf = 0; mf < 2; mf++)
#pragma unroll
        for (int nf = 0; nf < 4; nf++)
#pragma unroll
            for (int q = 0; q < 4; q++) acc[mf][nf][q] = 0.0f;

    int fr = tid >> 1;
    int fhalf = tid & 1;
    int grow = row0 + fr;
    bool aok = grow < N_NODES;
    const float* asrc = g_a1 + (size_t)grow * HID + fhalf * 16;
    const float* bbp = b1s + fhalf * 16;

    for (int kt = 0; kt < HID; kt += 32) {
        // A tile: relu(a1+b1) -> bf16 hi/lo
#pragma unroll
        for (int j = 0; j < 4; j++) {
            float4 v = make_float4(0.f, 0.f, 0.f, 0.f);
            if (aok) {
                v = *(const float4*)(asrc + kt + j * 4);
                v.x = fmaxf(v.x + bbp[kt + j * 4 + 0], 0.f);
                v.y = fmaxf(v.y + bbp[kt + j * 4 + 1], 0.f);
                v.z = fmaxf(v.z + bbp[kt + j * 4 + 2], 0.f);
                v.w = fmaxf(v.w + bbp[kt + j * 4 + 3], 0.f);
            }
            __nv_bfloat162 h01 = __floats2bfloat162_rn(v.x, v.y);
            __nv_bfloat162 h23 = __floats2bfloat162_rn(v.z, v.w);
            float2 f01 = __bfloat1622float2(h01);
            float2 f23 = __bfloat1622float2(h23);
            __nv_bfloat162 l01 = __floats2bfloat162_rn(v.x - f01.x, v.y - f01.y);
            __nv_bfloat162 l23 = __floats2bfloat162_rn(v.z - f23.x, v.w - f23.y);
            int eoff = fr * APAD + fhalf * 16 + j * 4;
            *(__nv_bfloat162*)&sAhi[eoff]     = h01;
            *(__nv_bfloat162*)&sAhi[eoff + 2] = h23;
            *(__nv_bfloat162*)&sAlo[eoff]     = l01;
            *(__nv_bfloat162*)&sAlo[eoff + 2] = l23;
        }
        // B tile: 64 n x 32 k, one 16B chunk per thread
        {
            int n = tid >> 2, c8 = tid & 3;
            const __nv_bfloat16* sh = g_B2hi + (size_t)n * HID + kt + c8 * 8;
            const __nv_bfloat16* sl = g_B2lo + (size_t)n * HID + kt + c8 * 8;
            *(uint4*)&sBhi[n * APAD + c8 * 8] = *(const uint4*)sh;
            *(uint4*)&sBlo[n * APAD + c8 * 8] = *(const uint4*)sl;
        }
        __syncthreads();

#pragma unroll
        for (int kf = 0; kf < 2; kf++) {
            int kk = kf * 16;
            uint32_t ahi[2][4], alo[2][4];
#pragma unroll
            for (int mf = 0; mf < 2; mf++) {
                uint32_t off = (uint32_t)((wm + mf * 16 + aRow) * APAD + kk + aK) * 2;
                ldm4(ahi[mf], aHiB + off);
                ldm4(alo[mf], aLoB + off);
            }
#pragma unroll
            for (int np = 0; np < 2; np++) {
                uint32_t bh[4], bl[4];
                uint32_t off = (uint32_t)((wn + np * 16 + bN) * APAD + kk + bK) * 2;
                ldm4(bh, bHiB + off);
                ldm4(bl, bLoB + off);
#pragma unroll
                for (int s = 0; s < 2; s++) {
                    int nf = np * 2 + s;
#pragma unroll
                    for (int mf = 0; mf < 2; mf++) {
                        mma_bf16(acc[mf][nf], ahi[mf], bh + s * 2);
                        mma_bf16(acc[mf][nf], ahi[mf], bl + s * 2);
                        mma_bf16(acc[mf][nf], alo[mf], bh + s * 2);
                    }
                }
            }
        }
        __syncthreads();
    }

    // epilogue: g_h2 (fp16) = dinv * C
    int g = lane >> 2, t4 = lane & 3;
#pragma unroll
    for (int mf = 0; mf < 2; mf++) {
        int r0 = row0 + wm + mf * 16 + g;
        int r1 = r0 + 8;
        float s0 = (r0 < N_NODES) ? g_dinv[r0] : 0.0f;
        float s1 = (r1 < N_NODES) ? g_dinv[r1] : 0.0f;
#pragma unroll
        for (int nf = 0; nf < 4; nf++) {
            int cb = wn + nf * 8 + t4 * 2;
            if (r0 < N_NODES)
                *(__half2*)(g_h2 + (size_t)r0 * OUTD + cb) =
                    __floats2half2_rn(s0 * acc[mf][nf][0], s0 * acc[mf][nf][1]);
            if (r1 < N_NODES)
                *(__half2*)(g_h2 + (size_t)r1 * OUTD + cb) =
                    __floats2half2_rn(s1 * acc[mf][nf][2], s1 * acc[mf][nf][3]);
        }
    }
}

// ---------------- layer-2 aggregation: warp per node, fp16 gathers ----------
__global__ void k_agg2(const float* __restrict__ b2, float* __restrict__ out) {
    int gw = (blockIdx.x * blockDim.x + threadIdx.x) >> 5;
    if (gw >= N_NODES) return;
    int lane = threadIdx.x & 31;
    int doff = lane * 2;

    float2 sf = __half22float2(*(const __half2*)(g_h2 + (size_t)gw * OUTD + doff));
    float2 acc0 = sf;
    float2 acc1 = make_float2(0.f, 0.f);

    int beg = g_off[gw];
    int end = beg + g_cnt[gw];
    int e = beg;
    for (; e + 2 <= end; e += 2) {
        int s0 = g_src[e], s1 = g_src[e + 1];
        float w0 = g_we[e], w1 = g_we[e + 1];
        float2 v0 = __half22float2(*(const __half2*)(g_h2 + (size_t)s0 * OUTD + doff));
        float2 v1 = __half22float2(*(const __half2*)(g_h2 + (size_t)s1 * OUTD + doff));
        acc0.x = fmaf(w0, v0.x, acc0.x); acc0.y = fmaf(w0, v0.y, acc0.y);
        acc1.x = fmaf(w1, v1.x, acc1.x); acc1.y = fmaf(w1, v1.y, acc1.y);
    }
    if (e < end) {
        int s0 = g_src[e];
        float w0 = g_we[e];
        float2 v0 = __half22float2(*(const __half2*)(g_h2 + (size_t)s0 * OUTD + doff));
        acc0.x = fmaf(w0, v0.x, acc0.x); acc0.y = fmaf(w0, v0.y, acc0.y);
    }
    float s = g_dinv[gw];
    float2 bb = ((const float2*)b2)[lane];
    float2 r = make_float2(fmaf(s, acc0.x + acc1.x, bb.x),
                           fmaf(s, acc0.y + acc1.y, bb.y));
    *(float2*)(out + (size_t)gw * OUTD + doff) = r;
}

// ---------------- launch ----------------
extern "C" void kernel_launch(void* const* d_in, const int* in_sizes, int n_in,
                              void* d_out, int out_size) {
    const float* x  = (const float*)d_in[0];
    const int*   ei = (const int*)d_in[1];   // int32 (JAX downgrades int64)
    const float* ew = (const float*)d_in[2];
    const float* W1 = (const float*)d_in[3];
    const float* b1 = (const float*)d_in[4];
    const float* W2 = (const float*)d_in[5];
    const float* b2 = (const float*)d_in[6];
    float*       out = (float*)d_out;

    const int* row = ei;
    const int* col = ei + N_EDGES;

    k_setup<<<(N_NODES + 255) / 256, 256>>>(W1, W2);                 // 0
    k_hist<<<(N_EDGES + 255) / 256, 256>>>(col, ew);                 // 1
    k_dinv<<<(N_NODES + 255) / 256, 256>>>();                        // 2
    k_gemm1_mma<<<(N_NODES + 127) / 128, 256>>>(x);                  // 3 (profiled slot)
    k_alloc<<<(N_NODES + 255) / 256, 256>>>();                       // 4
    k_fill<<<(N_EDGES + 255) / 256, 256>>>(row, col, ew);            // 5
    k_agg1<<<(N_NODES * 32 + 255) / 256, 256>>>();                   // 6
    k_gemm2_mma<<<(N_NODES + 127) / 128, 256>>>(b1);                 // 7
    k_agg2<<<(N_NODES * 32 + 255) / 256, 256>>>(b2, out);            // 8
}

// round 8
// speedup vs baseline: 3.9588x; 1.0506x over previous
#include <cuda_runtime.h>
#include <cuda_bf16.h>
#include <cuda_fp16.h>
#include <cstdint>

#define N_NODES 100000
#define N_EDGES 1600000
#define IN_DIM 256
#define HID 128
#define OUTD 64

// ---------------- scratch (device globals; no allocs allowed) ----------------
__device__ float g_deg[N_NODES];
__device__ float g_dinv[N_NODES];
__device__ int   g_cnt[N_NODES];
__device__ int   g_off[N_NODES];
__device__ int   g_cur[N_NODES];
__device__ int   g_total;
__device__ int   g_src[N_EDGES];
__device__ float g_we[N_EDGES];
__device__ __nv_bfloat16 g_B1hi[HID * IN_DIM];  // W1 split, [n][k]
__device__ __nv_bfloat16 g_B1lo[HID * IN_DIM];
__device__ __nv_bfloat16 g_B2hi[OUTD * HID];    // W2 split, [n][k]
__device__ __nv_bfloat16 g_B2lo[OUTD * HID];
__device__ __half g_h1[(size_t)N_NODES * HID];  // fp16: dinv * (x @ W1)
__device__ float  g_a1[(size_t)N_NODES * HID];  // f32 aggregated layer-1
__device__ __half g_h2[(size_t)N_NODES * OUTD]; // fp16: dinv * (relu(a1+b1) @ W2)

__device__ __forceinline__ uint32_t smem_u32(const void* p) {
    uint32_t a;
    asm("{ .reg .u64 t; cvta.to.shared.u64 t, %1; cvt.u32.u64 %0, t; }" : "=r"(a) : "l"(p));
    return a;
}
__device__ __forceinline__ void ldm4(uint32_t* r, uint32_t addr) {
    asm volatile("ldmatrix.sync.aligned.m8n8.x4.shared.b16 {%0,%1,%2,%3}, [%4];"
                 : "=r"(r[0]), "=r"(r[1]), "=r"(r[2]), "=r"(r[3]) : "r"(addr));
}
__device__ __forceinline__ void mma_bf16(float* d, const uint32_t* a, const uint32_t* b) {
    asm volatile(
        "mma.sync.aligned.m16n8k16.row.col.f32.bf16.bf16.f32 "
        "{%0,%1,%2,%3}, {%4,%5,%6,%7}, {%8,%9}, {%0,%1,%2,%3};"
        : "+f"(d[0]), "+f"(d[1]), "+f"(d[2]), "+f"(d[3])
        : "r"(a[0]), "r"(a[1]), "r"(a[2]), "r"(a[3]), "r"(b[0]), "r"(b[1]));
}
__device__ __forceinline__ float4 ld_h4(const __half* p) {
    uint2 u = *(const uint2*)p;
    __half2 a = *(__half2*)&u.x, b = *(__half2*)&u.y;
    float2 fa = __half22float2(a), fb = __half22float2(b);
    return make_float4(fa.x, fa.y, fb.x, fb.y);
}
__device__ __forceinline__ void cp_async16(void* smem, const void* gmem) {
    unsigned s = (unsigned)__cvta_generic_to_shared(smem);
    asm volatile("cp.async.cg.shared.global [%0], [%1], 16;" :: "r"(s), "l"(gmem));
}
#define CP_COMMIT() asm volatile("cp.async.commit_group;")
#define CP_WAIT0()  asm volatile("cp.async.wait_group 0;")

// ---------------- fused setup: deg/cnt init + W1/W2 bf16 hi-lo splits -------
__global__ void k_setup(const float* __restrict__ W1, const float* __restrict__ W2) {
    int i = blockIdx.x * blockDim.x + threadIdx.x;
    if (i < N_NODES) { g_deg[i] = 1.0f; g_cnt[i] = 0; }
    if (i == 0) g_total = 0;
    if (i < HID * IN_DIM) {
        int n = i >> 8, k = i & 255;
        float w = W1[(size_t)k * HID + n];
        __nv_bfloat16 h = __float2bfloat16(w);
        g_B1hi[i] = h;
        g_B1lo[i] = __float2bfloat16(w - __bfloat162float(h));
    }
    if (i < OUTD * HID) {
        int n = i >> 7, k = i & 127;
        float w = W2[(size_t)k * OUTD + n];
        __nv_bfloat16 h = __float2bfloat16(w);
        g_B2hi[i] = h;
        g_B2lo[i] = __float2bfloat16(w - __bfloat162float(h));
    }
}

// ---------------- histogram: 2 edges per thread ----------------
__global__ void k_hist(const int* __restrict__ col, const float* __restrict__ w) {
    int e = (blockIdx.x * blockDim.x + threadIdx.x) * 2;
    if (e + 1 < N_EDGES) {
        int2 c = *(const int2*)(col + e);
        float2 ww = *(const float2*)(w + e);
        atomicAdd(&g_deg[c.x], ww.x);
        atomicAdd(&g_cnt[c.x], 1);
        atomicAdd(&g_deg[c.y], ww.y);
        atomicAdd(&g_cnt[c.y], 1);
    } else if (e < N_EDGES) {
        atomicAdd(&g_deg[col[e]], w[e]);
        atomicAdd(&g_cnt[col[e]], 1);
    }
}

// ---------------- fused dinv + CSR bucket allocation ----------------
__global__ void __launch_bounds__(256) k_dinvalloc() {
    __shared__ int sc[256];
    __shared__ int sbase;
    int tid = threadIdx.x;
    int i = blockIdx.x * 256 + tid;
    if (i < N_NODES) {
        float d = g_deg[i];
        g_dinv[i] = d > 0.0f ? rsqrtf(d) : 0.0f;
    }
    int v = (i < N_NODES) ? g_cnt[i] : 0;
    sc[tid] = v;
    __syncthreads();
#pragma unroll
    for (int off = 1; off < 256; off <<= 1) {
        int t = (tid >= off) ? sc[tid - off] : 0;
        __syncthreads();
        sc[tid] += t;
        __syncthreads();
    }
    if (tid == 255) sbase = atomicAdd(&g_total, sc[255]);
    __syncthreads();
    if (i < N_NODES) {
        int base = sbase + sc[tid] - v;
        g_off[i] = base;
        g_cur[i] = base;
    }
}

// ---------------- CSR fill: 2 edges per thread ----------------
__global__ void k_fill(const int* __restrict__ row, const int* __restrict__ col,
                       const float* __restrict__ w) {
    int e = (blockIdx.x * blockDim.x + threadIdx.x) * 2;
    if (e + 1 < N_EDGES) {
        int2 r = *(const int2*)(row + e);
        int2 c = *(const int2*)(col + e);
        float2 ww = *(const float2*)(w + e);
        int p0 = atomicAdd(&g_cur[c.x], 1);
        g_src[p0] = r.x; g_we[p0] = ww.x;
        int p1 = atomicAdd(&g_cur[c.y], 1);
        g_src[p1] = r.y; g_we[p1] = ww.y;
    } else if (e < N_EDGES) {
        int pos = atomicAdd(&g_cur[col[e]], 1);
        g_src[pos] = row[e]; g_we[pos] = w[e];
    }
}

// ---------------- GEMM1: pipelined bf16 3-term split HMMA ----------------
// C[100000,128] = x @ W1; BM=128 BN=128 BK=32, 256 thr (8 warps 4x2).
// B via cp.async (overlaps A convert), A reg-prefetched across iterations.
#define APAD 40
__global__ void __launch_bounds__(256, 2) k_gemm1_mma(const float* __restrict__ x) {
    __shared__ __align__(16) __nv_bfloat16 sAhi[128 * APAD];
    __shared__ __align__(16) __nv_bfloat16 sAlo[128 * APAD];
    __shared__ __align__(16) __nv_bfloat16 sBhi[128 * APAD];
    __shared__ __align__(16) __nv_bfloat16 sBlo[128 * APAD];

    int tid = threadIdx.x;
    int lane = tid & 31;
    int wid = tid >> 5;
    int wm = (wid & 3) * 32;
    int wn = (wid >> 2) * 64;
    int row0 = blockIdx.x * 128;

    uint32_t aHiB = smem_u32(sAhi);
    uint32_t aLoB = smem_u32(sAlo);
    uint32_t bHiB = smem_u32(sBhi);
    uint32_t bLoB = smem_u32(sBlo);

    int within = lane & 7, sub = lane >> 3;
    int aRow = within + (sub & 1) * 8;
    int aK   = (sub >> 1) * 8;
    int bN   = within + (sub >> 1) * 8;
    int bK   = (sub & 1) * 8;

    float acc[2][8][4];
#pragma unroll
    for (int mf = 0; mf < 2; mf++)
#pragma unroll
        for (int nf = 0; nf < 8; nf++)
#pragma unroll
            for (int q = 0; q < 4; q++) acc[mf][nf][q] = 0.0f;

    int fr = tid >> 1;
    int fhalf = tid & 1;
    int grow = row0 + fr;
    bool aok = grow < N_NODES;
    const float* asrc = x + (size_t)grow * IN_DIM + fhalf * 16;
    const float4 z4 = make_float4(0.f, 0.f, 0.f, 0.f);

    // B cp.async fixed per-thread chunk coords
    int bn0 = tid >> 2, bc0 = (tid & 3) * 8;            // chunk 0 (n 0..63)
    int bn1 = (tid + 256) >> 2;                          // chunk 1 (n 64..127)

    // prefetch A(0)
    float4 ra[4];
#pragma unroll
    for (int j = 0; j < 4; j++) ra[j] = aok ? *(const float4*)(asrc + j * 4) : z4;

#pragma unroll 1
    for (int t = 0; t < 8; t++) {
        int kt = t * 32;
        // B tiles via cp.async (L2-resident after first wave)
        cp_async16(&sBhi[bn0 * APAD + bc0], g_B1hi + (size_t)bn0 * IN_DIM + kt + bc0);
        cp_async16(&sBlo[bn0 * APAD + bc0], g_B1lo + (size_t)bn0 * IN_DIM + kt + bc0);
        cp_async16(&sBhi[bn1 * APAD + bc0], g_B1hi + (size_t)bn1 * IN_DIM + kt + bc0);
        cp_async16(&sBlo[bn1 * APAD + bc0], g_B1lo + (size_t)bn1 * IN_DIM + kt + bc0);
        CP_COMMIT();

        // A convert + store from prefetched regs
#pragma unroll
        for (int j = 0; j < 4; j++) {
            float4 v = ra[j];
            __nv_bfloat162 h01 = __floats2bfloat162_rn(v.x, v.y);
            __nv_bfloat162 h23 = __floats2bfloat162_rn(v.z, v.w);
            float2 f01 = __bfloat1622float2(h01);
            float2 f23 = __bfloat1622float2(h23);
            __nv_bfloat162 l01 = __floats2bfloat162_rn(v.x - f01.x, v.y - f01.y);
            __nv_bfloat162 l23 = __floats2bfloat162_rn(v.z - f23.x, v.w - f23.y);
            int eoff = fr * APAD + fhalf * 16 + j * 4;
            *(__nv_bfloat162*)&sAhi[eoff]     = h01;
            *(__nv_bfloat162*)&sAhi[eoff + 2] = h23;
            *(__nv_bfloat162*)&sAlo[eoff]     = l01;
            *(__nv_bfloat162*)&sAlo[eoff + 2] = l23;
        }
        CP_WAIT0();
        __syncthreads();

        // prefetch A(t+1): LDGs retire under the MMA block below
        if (t < 7) {
#pragma unroll
            for (int j = 0; j < 4; j++)
                ra[j] = aok ? *(const float4*)(asrc + kt + 32 + j * 4) : z4;
        }

#pragma unroll
        for (int kf = 0; kf < 2; kf++) {
            int kk = kf * 16;
            uint32_t ahi[2][4], alo[2][4];
#pragma unroll
            for (int mf = 0; mf < 2; mf++) {
                uint32_t off = (uint32_t)((wm + mf * 16 + aRow) * APAD + kk + aK) * 2;
                ldm4(ahi[mf], aHiB + off);
                ldm4(alo[mf], aLoB + off);
            }
#pragma unroll
            for (int np = 0; np < 4; np++) {
                uint32_t bh[4], bl[4];
                uint32_t off = (uint32_t)((wn + np * 16 + bN) * APAD + kk + bK) * 2;
                ldm4(bh, bHiB + off);
                ldm4(bl, bLoB + off);
#pragma unroll
                for (int s = 0; s < 2; s++) {
                    int nf = np * 2 + s;
#pragma unroll
                    for (int mf = 0; mf < 2; mf++) {
                        mma_bf16(acc[mf][nf], ahi[mf], bh + s * 2);
                        mma_bf16(acc[mf][nf], ahi[mf], bl + s * 2);
                        mma_bf16(acc[mf][nf], alo[mf], bh + s * 2);
                    }
                }
            }
        }
        __syncthreads();
    }

    // epilogue: g_h1 (fp16) = dinv * C
    int g = lane >> 2, t4 = lane & 3;
#pragma unroll
    for (int mf = 0; mf < 2; mf++) {
        int r0 = row0 + wm + mf * 16 + g;
        int r1 = r0 + 8;
        float s0 = (r0 < N_NODES) ? g_dinv[r0] : 0.0f;
        float s1 = (r1 < N_NODES) ? g_dinv[r1] : 0.0f;
#pragma unroll
        for (int nf = 0; nf < 8; nf++) {
            int cb = wn + nf * 8 + t4 * 2;
            if (r0 < N_NODES)
                *(__half2*)(g_h1 + (size_t)r0 * HID + cb) =
                    __floats2half2_rn(s0 * acc[mf][nf][0], s0 * acc[mf][nf][1]);
            if (r1 < N_NODES)
                *(__half2*)(g_h1 + (size_t)r1 * HID + cb) =
                    __floats2half2_rn(s1 * acc[mf][nf][2], s1 * acc[mf][nf][3]);
        }
    }
}

// ---------------- layer-1 aggregation: warp per node, fp16 gathers ----------
__global__ void k_agg1() {
    int gw = (blockIdx.x * blockDim.x + threadIdx.x) >> 5;
    if (gw >= N_NODES) return;
    int lane = threadIdx.x & 31;
    const __half* hbase = g_h1;
    int doff = lane * 4;

    float4 acc0 = ld_h4(hbase + (size_t)gw * HID + doff);
    float4 acc1 = make_float4(0.f, 0.f, 0.f, 0.f);

    int beg = g_off[gw];
    int end = beg + g_cnt[gw];
    int e = beg;
    for (; e + 2 <= end; e += 2) {
        int s0 = g_src[e], s1 = g_src[e + 1];
        float w0 = g_we[e], w1 = g_we[e + 1];
        float4 v0 = ld_h4(hbase + (size_t)s0 * HID + doff);
        float4 v1 = ld_h4(hbase + (size_t)s1 * HID + doff);
        acc0.x = fmaf(w0, v0.x, acc0.x); acc0.y = fmaf(w0, v0.y, acc0.y);
        acc0.z = fmaf(w0, v0.z, acc0.z); acc0.w = fmaf(w0, v0.w, acc0.w);
        acc1.x = fmaf(w1, v1.x, acc1.x); acc1.y = fmaf(w1, v1.y, acc1.y);
        acc1.z = fmaf(w1, v1.z, acc1.z); acc1.w = fmaf(w1, v1.w, acc1.w);
    }
    if (e < end) {
        int s0 = g_src[e];
        float w0 = g_we[e];
        float4 v0 = ld_h4(hbase + (size_t)s0 * HID + doff);
        acc0.x = fmaf(w0, v0.x, acc0.x); acc0.y = fmaf(w0, v0.y, acc0.y);
        acc0.z = fmaf(w0, v0.z, acc0.z); acc0.w = fmaf(w0, v0.w, acc0.w);
    }
    float s = g_dinv[gw];
    float4 r = make_float4(s * (acc0.x + acc1.x), s * (acc0.y + acc1.y),
                           s * (acc0.z + acc1.z), s * (acc0.w + acc1.w));
    *(float4*)(g_a1 + (size_t)gw * HID + doff) = r;
}

// ---------------- GEMM2 via mma.sync bf16 3-term split ----------------
__global__ void __launch_bounds__(256) k_gemm2_mma(const float* __restrict__ b1) {
    __shared__ __align__(16) __nv_bfloat16 sAhi[128 * APAD];
    __shared__ __align__(16) __nv_bfloat16 sAlo[128 * APAD];
    __shared__ __align__(16) __nv_bfloat16 sBhi[64 * APAD];
    __shared__ __align__(16) __nv_bfloat16 sBlo[64 * APAD];
    __shared__ float b1s[HID];

    int tid = threadIdx.x;
    int lane = tid & 31;
    int wid = tid >> 5;
    int wm = (wid & 3) * 32;
    int wn = (wid >> 2) * 32;
    int row0 = blockIdx.x * 128;

    if (tid < HID) b1s[tid] = b1[tid];
    __syncthreads();

    uint32_t aHiB = smem_u32(sAhi);
    uint32_t aLoB = smem_u32(sAlo);
    uint32_t bHiB = smem_u32(sBhi);
    uint32_t bLoB = smem_u32(sBlo);

    int within = lane & 7, sub = lane >> 3;
    int aRow = within + (sub & 1) * 8;
    int aK   = (sub >> 1) * 8;
    int bN   = within + (sub >> 1) * 8;
    int bK   = (sub & 1) * 8;

    float acc[2][4][4];
#pragma unroll
    for (int mf = 0; mf < 2; mf++)
#pragma unroll
        for (int nf = 0; nf < 4; nf++)
#pragma unroll
            for (int q = 0; q < 4; q++) acc[mf][nf][q] = 0.0f;

    int fr = tid >> 1;
    int fhalf = tid & 1;
    int grow = row0 + fr;
    bool aok = grow < N_NODES;
    const float* asrc = g_a1 + (size_t)grow * HID + fhalf * 16;
    const float* bbp = b1s + fhalf * 16;

    for (int kt = 0; kt < HID; kt += 32) {
#pragma unroll
        for (int j = 0; j < 4; j++) {
            float4 v = make_float4(0.f, 0.f, 0.f, 0.f);
            if (aok) {
                v = *(const float4*)(asrc + kt + j * 4);
                v.x = fmaxf(v.x + bbp[kt + j * 4 + 0], 0.f);
                v.y = fmaxf(v.y + bbp[kt + j * 4 + 1], 0.f);
                v.z = fmaxf(v.z + bbp[kt + j * 4 + 2], 0.f);
                v.w = fmaxf(v.w + bbp[kt + j * 4 + 3], 0.f);
            }
            __nv_bfloat162 h01 = __floats2bfloat162_rn(v.x, v.y);
            __nv_bfloat162 h23 = __floats2bfloat162_rn(v.z, v.w);
            float2 f01 = __bfloat1622float2(h01);
            float2 f23 = __bfloat1622float2(h23);
            __nv_bfloat162 l01 = __floats2bfloat162_rn(v.x - f01.x, v.y - f01.y);
            __nv_bfloat162 l23 = __floats2bfloat162_rn(v.z - f23.x, v.w - f23.y);
            int eoff = fr * APAD + fhalf * 16 + j * 4;
            *(__nv_bfloat162*)&sAhi[eoff]     = h01;
            *(__nv_bfloat162*)&sAhi[eoff + 2] = h23;
            *(__nv_bfloat162*)&sAlo[eoff]     = l01;
            *(__nv_bfloat162*)&sAlo[eoff + 2] = l23;
        }
        {
            int n = tid >> 2, c8 = tid & 3;
            const __nv_bfloat16* sh = g_B2hi + (size_t)n * HID + kt + c8 * 8;
            const __nv_bfloat16* sl = g_B2lo + (size_t)n * HID + kt + c8 * 8;
            *(uint4*)&sBhi[n * APAD + c8 * 8] = *(const uint4*)sh;
            *(uint4*)&sBlo[n * APAD + c8 * 8] = *(const uint4*)sl;
        }
        __syncthreads();

#pragma unroll
        for (int kf = 0; kf < 2; kf++) {
            int kk = kf * 16;
            uint32_t ahi[2][4], alo[2][4];
#pragma unroll
            for (int mf = 0; mf < 2; mf++) {
                uint32_t off = (uint32_t)((wm + mf * 16 + aRow) * APAD + kk + aK) * 2;
                ldm4(ahi[mf], aHiB + off);
                ldm4(alo[mf], aLoB + off);
            }
#pragma unroll
            for (int np = 0; np < 2; np++) {
                uint32_t bh[4], bl[4];
                uint32_t off = (uint32_t)((wn + np * 16 + bN) * APAD + kk + bK) * 2;
                ldm4(bh, bHiB + off);
                ldm4(bl, bLoB + off);
#pragma unroll
                for (int s = 0; s < 2; s++) {
                    int nf = np * 2 + s;
#pragma unroll
                    for (int mf = 0; mf < 2; mf++) {
                        mma_bf16(acc[mf][nf], ahi[mf], bh + s * 2);
                        mma_bf16(acc[mf][nf], ahi[mf], bl + s * 2);
                        mma_bf16(acc[mf][nf], alo[mf], bh + s * 2);
                    }
                }
            }
        }
        __syncthreads();
    }

    int g = lane >> 2, t4 = lane & 3;
#pragma unroll
    for (int mf = 0; mf < 2; mf++) {
        int r0 = row0 + wm + mf * 16 + g;
        int r1 = r0 + 8;
        float s0 = (r0 < N_NODES) ? g_dinv[r0] : 0.0f;
        float s1 = (r1 < N_NODES) ? g_dinv[r1] : 0.0f;
#pragma unroll
        for (int nf = 0; nf < 4; nf++) {
            int cb = wn + nf * 8 + t4 * 2;
            if (r0 < N_NODES)
                *(__half2*)(g_h2 + (size_t)r0 * OUTD + cb) =
                    __floats2half2_rn(s0 * acc[mf][nf][0], s0 * acc[mf][nf][1]);
            if (r1 < N_NODES)
                *(__half2*)(g_h2 + (size_t)r1 * OUTD + cb) =
                    __floats2half2_rn(s1 * acc[mf][nf][2], s1 * acc[mf][nf][3]);
        }
    }
}

// ---------------- layer-2 aggregation: warp per node, fp16 gathers ----------
__global__ void k_agg2(const float* __restrict__ b2, float* __restrict__ out) {
    int gw = (blockIdx.x * blockDim.x + threadIdx.x) >> 5;
    if (gw >= N_NODES) return;
    int lane = threadIdx.x & 31;
    int doff = lane * 2;

    float2 acc0 = __half22float2(*(const __half2*)(g_h2 + (size_t)gw * OUTD + doff));
    float2 acc1 = make_float2(0.f, 0.f);

    int beg = g_off[gw];
    int end = beg + g_cnt[gw];
    int e = beg;
    for (; e + 2 <= end; e += 2) {
        int s0 = g_src[e], s1 = g_src[e + 1];
        float w0 = g_we[e], w1 = g_we[e + 1];
        float2 v0 = __half22float2(*(const __half2*)(g_h2 + (size_t)s0 * OUTD + doff));
        float2 v1 = __half22float2(*(const __half2*)(g_h2 + (size_t)s1 * OUTD + doff));
        acc0.x = fmaf(w0, v0.x, acc0.x); acc0.y = fmaf(w0, v0.y, acc0.y);
        acc1.x = fmaf(w1, v1.x, acc1.x); acc1.y = fmaf(w1, v1.y, acc1.y);
    }
    if (e < end) {
        int s0 = g_src[e];
        float w0 = g_we[e];
        float2 v0 = __half22float2(*(const __half2*)(g_h2 + (size_t)s0 * OUTD + doff));
        acc0.x = fmaf(w0, v0.x, acc0.x); acc0.y = fmaf(w0, v0.y, acc0.y);
    }
    float s = g_dinv[gw];
    float2 bb = ((const float2*)b2)[lane];
    float2 r = make_float2(fmaf(s, acc0.x + acc1.x, bb.x),
                           fmaf(s, acc0.y + acc1.y, bb.y));
    *(float2*)(out + (size_t)gw * OUTD + doff) = r;
}

// ---------------- launch ----------------
extern "C" void kernel_launch(void* const* d_in, const int* in_sizes, int n_in,
                              void* d_out, int out_size) {
    const float* x  = (const float*)d_in[0];
    const int*   ei = (const int*)d_in[1];   // int32 (JAX downgrades int64)
    const float* ew = (const float*)d_in[2];
    const float* W1 = (const float*)d_in[3];
    const float* b1 = (const float*)d_in[4];
    const float* W2 = (const float*)d_in[5];
    const float* b2 = (const float*)d_in[6];
    float*       out = (float*)d_out;

    const int* row = ei;
    const int* col = ei + N_EDGES;

    k_setup<<<(N_NODES + 255) / 256, 256>>>(W1, W2);                 // 0
    k_hist<<<(N_EDGES / 2 + 255) / 256, 256>>>(col, ew);             // 1
    k_dinvalloc<<<(N_NODES + 255) / 256, 256>>>();                   // 2
    k_gemm1_mma<<<(N_NODES + 127) / 128, 256>>>(x);                  // 3 (profiled slot)
    k_fill<<<(N_EDGES / 2 + 255) / 256, 256>>>(row, col, ew);        // 4
    k_agg1<<<(N_NODES * 32 + 255) / 256, 256>>>();                   // 5
    k_gemm2_mma<<<(N_NODES + 127) / 128, 256>>>(b1);                 // 6
    k_agg2<<<(N_NODES * 32 + 255) / 256, 256>>>(b2, out);            // 7
}

// round 9
// speedup vs baseline: 3.9699x; 1.0028x over previous
#include <cuda_runtime.h>
#include <cuda_bf16.h>
#include <cuda_fp16.h>
#include <cstdint>

#define N_NODES 100000
#define N_EDGES 1600000
#define IN_DIM 256
#define HID 128
#define OUTD 64

// ---------------- scratch (device globals; no allocs allowed) ----------------
__device__ float g_deg[N_NODES];
__device__ float g_dinv[N_NODES];
__device__ int   g_cnt[N_NODES];
__device__ int   g_off[N_NODES];
__device__ int   g_cur[N_NODES];
__device__ int   g_total;
__device__ int   g_src[N_EDGES];
__device__ float g_we[N_EDGES];     // pre-normalized: w * dinv[col] * dinv[row]
__device__ __nv_bfloat16 g_B1hi[HID * IN_DIM];  // W1 split, [n][k]
__device__ __nv_bfloat16 g_B1lo[HID * IN_DIM];
__device__ __nv_bfloat16 g_B2hi[OUTD * HID];    // W2 split, [n][k]
__device__ __nv_bfloat16 g_B2lo[OUTD * HID];
__device__ __half g_h1[(size_t)N_NODES * HID];  // fp16: x @ W1 (UNscaled)
__device__ float  g_a1[(size_t)N_NODES * HID];  // f32 aggregated layer-1
__device__ __half g_h2[(size_t)N_NODES * OUTD]; // fp16: relu(a1+b1) @ W2 (UNscaled)

__device__ __forceinline__ uint32_t smem_u32(const void* p) {
    uint32_t a;
    asm("{ .reg .u64 t; cvta.to.shared.u64 t, %1; cvt.u32.u64 %0, t; }" : "=r"(a) : "l"(p));
    return a;
}
__device__ __forceinline__ void ldm4(uint32_t* r, uint32_t addr) {
    asm volatile("ldmatrix.sync.aligned.m8n8.x4.shared.b16 {%0,%1,%2,%3}, [%4];"
                 : "=r"(r[0]), "=r"(r[1]), "=r"(r[2]), "=r"(r[3]) : "r"(addr));
}
__device__ __forceinline__ void mma_bf16(float* d, const uint32_t* a, const uint32_t* b) {
    asm volatile(
        "mma.sync.aligned.m16n8k16.row.col.f32.bf16.bf16.f32 "
        "{%0,%1,%2,%3}, {%4,%5,%6,%7}, {%8,%9}, {%0,%1,%2,%3};"
        : "+f"(d[0]), "+f"(d[1]), "+f"(d[2]), "+f"(d[3])
        : "r"(a[0]), "r"(a[1]), "r"(a[2]), "r"(a[3]), "r"(b[0]), "r"(b[1]));
}
__device__ __forceinline__ float4 ld_h4(const __half* p) {
    uint2 u = *(const uint2*)p;
    __half2 a = *(__half2*)&u.x, b = *(__half2*)&u.y;
    float2 fa = __half22float2(a), fb = __half22float2(b);
    return make_float4(fa.x, fa.y, fb.x, fb.y);
}
__device__ __forceinline__ void cp_async16(void* smem, const void* gmem) {
    unsigned s = (unsigned)__cvta_generic_to_shared(smem);
    asm volatile("cp.async.cg.shared.global [%0], [%1], 16;" :: "r"(s), "l"(gmem));
}
#define CP_COMMIT() asm volatile("cp.async.commit_group;")
#define CP_WAIT0()  asm volatile("cp.async.wait_group 0;")

// ---------------- fused setup: deg/cnt init + W1/W2 bf16 hi-lo splits -------
__global__ void k_setup(const float* __restrict__ W1, const float* __restrict__ W2) {
    int i = blockIdx.x * blockDim.x + threadIdx.x;
    if (i < N_NODES) { g_deg[i] = 1.0f; g_cnt[i] = 0; }
    if (i == 0) g_total = 0;
    if (i < HID * IN_DIM) {
        int n = i >> 8, k = i & 255;
        float w = W1[(size_t)k * HID + n];
        __nv_bfloat16 h = __float2bfloat16(w);
        g_B1hi[i] = h;
        g_B1lo[i] = __float2bfloat16(w - __bfloat162float(h));
    }
    if (i < OUTD * HID) {
        int n = i >> 7, k = i & 127;
        float w = W2[(size_t)k * OUTD + n];
        __nv_bfloat16 h = __float2bfloat16(w);
        g_B2hi[i] = h;
        g_B2lo[i] = __float2bfloat16(w - __bfloat162float(h));
    }
}

// ---------------- histogram: 2 edges per thread ----------------
__global__ void k_hist(const int* __restrict__ col, const float* __restrict__ w) {
    int e = (blockIdx.x * blockDim.x + threadIdx.x) * 2;
    if (e + 1 < N_EDGES) {
        int2 c = *(const int2*)(col + e);
        float2 ww = *(const float2*)(w + e);
        atomicAdd(&g_deg[c.x], ww.x);
        atomicAdd(&g_cnt[c.x], 1);
        atomicAdd(&g_deg[c.y], ww.y);
        atomicAdd(&g_cnt[c.y], 1);
    } else if (e < N_EDGES) {
        atomicAdd(&g_deg[col[e]], w[e]);
        atomicAdd(&g_cnt[col[e]], 1);
    }
}

// ---------------- fused dinv + CSR bucket allocation ----------------
__global__ void __launch_bounds__(256) k_dinvalloc() {
    __shared__ int sc[256];
    __shared__ int sbase;
    int tid = threadIdx.x;
    int i = blockIdx.x * 256 + tid;
    if (i < N_NODES) {
        float d = g_deg[i];
        g_dinv[i] = d > 0.0f ? rsqrtf(d) : 0.0f;
    }
    int v = (i < N_NODES) ? g_cnt[i] : 0;
    sc[tid] = v;
    __syncthreads();
#pragma unroll
    for (int off = 1; off < 256; off <<= 1) {
        int t = (tid >= off) ? sc[tid - off] : 0;
        __syncthreads();
        sc[tid] += t;
        __syncthreads();
    }
    if (tid == 255) sbase = atomicAdd(&g_total, sc[255]);
    __syncthreads();
    if (i < N_NODES) {
        int base = sbase + sc[tid] - v;
        g_off[i] = base;
        g_cur[i] = base;
    }
}

// ---------------- CSR fill: 2 edges per thread, fold dinv into weight -------
__global__ void k_fill(const int* __restrict__ row, const int* __restrict__ col,
                       const float* __restrict__ w) {
    int e = (blockIdx.x * blockDim.x + threadIdx.x) * 2;
    if (e + 1 < N_EDGES) {
        int2 r = *(const int2*)(row + e);
        int2 c = *(const int2*)(col + e);
        float2 ww = *(const float2*)(w + e);
        int p0 = atomicAdd(&g_cur[c.x], 1);
        g_src[p0] = r.x; g_we[p0] = ww.x * g_dinv[c.x] * g_dinv[r.x];
        int p1 = atomicAdd(&g_cur[c.y], 1);
        g_src[p1] = r.y; g_we[p1] = ww.y * g_dinv[c.y] * g_dinv[r.y];
    } else if (e < N_EDGES) {
        int pos = atomicAdd(&g_cur[col[e]], 1);
        g_src[pos] = row[e];
        g_we[pos] = w[e] * g_dinv[col[e]] * g_dinv[row[e]];
    }
}

// ---------------- GEMM1: pipelined bf16 3-term split HMMA (dinv-free) -------
#define APAD 40
__global__ void __launch_bounds__(256, 2) k_gemm1_mma(const float* __restrict__ x) {
    __shared__ __align__(16) __nv_bfloat16 sAhi[128 * APAD];
    __shared__ __align__(16) __nv_bfloat16 sAlo[128 * APAD];
    __shared__ __align__(16) __nv_bfloat16 sBhi[128 * APAD];
    __shared__ __align__(16) __nv_bfloat16 sBlo[128 * APAD];

    int tid = threadIdx.x;
    int lane = tid & 31;
    int wid = tid >> 5;
    int wm = (wid & 3) * 32;
    int wn = (wid >> 2) * 64;
    int row0 = blockIdx.x * 128;

    uint32_t aHiB = smem_u32(sAhi);
    uint32_t aLoB = smem_u32(sAlo);
    uint32_t bHiB = smem_u32(sBhi);
    uint32_t bLoB = smem_u32(sBlo);

    int within = lane & 7, sub = lane >> 3;
    int aRow = within + (sub & 1) * 8;
    int aK   = (sub >> 1) * 8;
    int bN   = within + (sub >> 1) * 8;
    int bK   = (sub & 1) * 8;

    float acc[2][8][4];
#pragma unroll
    for (int mf = 0; mf < 2; mf++)
#pragma unroll
        for (int nf = 0; nf < 8; nf++)
#pragma unroll
            for (int q = 0; q < 4; q++) acc[mf][nf][q] = 0.0f;

    int fr = tid >> 1;
    int fhalf = tid & 1;
    int grow = row0 + fr;
    bool aok = grow < N_NODES;
    const float* asrc = x + (size_t)grow * IN_DIM + fhalf * 16;
    const float4 z4 = make_float4(0.f, 0.f, 0.f, 0.f);

    int bn0 = tid >> 2, bc0 = (tid & 3) * 8;
    int bn1 = (tid + 256) >> 2;

    float4 ra[4];
#pragma unroll
    for (int j = 0; j < 4; j++) ra[j] = aok ? *(const float4*)(asrc + j * 4) : z4;

#pragma unroll 1
    for (int t = 0; t < 8; t++) {
        int kt = t * 32;
        cp_async16(&sBhi[bn0 * APAD + bc0], g_B1hi + (size_t)bn0 * IN_DIM + kt + bc0);
        cp_async16(&sBlo[bn0 * APAD + bc0], g_B1lo + (size_t)bn0 * IN_DIM + kt + bc0);
        cp_async16(&sBhi[bn1 * APAD + bc0], g_B1hi + (size_t)bn1 * IN_DIM + kt + bc0);
        cp_async16(&sBlo[bn1 * APAD + bc0], g_B1lo + (size_t)bn1 * IN_DIM + kt + bc0);
        CP_COMMIT();

#pragma unroll
        for (int j = 0; j < 4; j++) {
            float4 v = ra[j];
            __nv_bfloat162 h01 = __floats2bfloat162_rn(v.x, v.y);
            __nv_bfloat162 h23 = __floats2bfloat162_rn(v.z, v.w);
            float2 f01 = __bfloat1622float2(h01);
            float2 f23 = __bfloat1622float2(h23);
            __nv_bfloat162 l01 = __floats2bfloat162_rn(v.x - f01.x, v.y - f01.y);
            __nv_bfloat162 l23 = __floats2bfloat162_rn(v.z - f23.x, v.w - f23.y);
            int eoff = fr * APAD + fhalf * 16 + j * 4;
            *(__nv_bfloat162*)&sAhi[eoff]     = h01;
            *(__nv_bfloat162*)&sAhi[eoff + 2] = h23;
            *(__nv_bfloat162*)&sAlo[eoff]     = l01;
            *(__nv_bfloat162*)&sAlo[eoff + 2] = l23;
        }
        CP_WAIT0();
        __syncthreads();

        if (t < 7) {
#pragma unroll
            for (int j = 0; j < 4; j++)
                ra[j] = aok ? *(const float4*)(asrc + kt + 32 + j * 4) : z4;
        }

#pragma unroll
        for (int kf = 0; kf < 2; kf++) {
            int kk = kf * 16;
            uint32_t ahi[2][4], alo[2][4];
#pragma unroll
            for (int mf = 0; mf < 2; mf++) {
                uint32_t off = (uint32_t)((wm + mf * 16 + aRow) * APAD + kk + aK) * 2;
                ldm4(ahi[mf], aHiB + off);
                ldm4(alo[mf], aLoB + off);
            }
#pragma unroll
            for (int np = 0; np < 4; np++) {
                uint32_t bh[4], bl[4];
                uint32_t off = (uint32_t)((wn + np * 16 + bN) * APAD + kk + bK) * 2;
                ldm4(bh, bHiB + off);
                ldm4(bl, bLoB + off);
#pragma unroll
                for (int s = 0; s < 2; s++) {
                    int nf = np * 2 + s;
#pragma unroll
                    for (int mf = 0; mf < 2; mf++) {
                        mma_bf16(acc[mf][nf], ahi[mf], bh + s * 2);
                        mma_bf16(acc[mf][nf], ahi[mf], bl + s * 2);
                        mma_bf16(acc[mf][nf], alo[mf], bh + s * 2);
                    }
                }
            }
        }
        __syncthreads();
    }

    // epilogue: g_h1 (fp16) = C, unscaled
    int g = lane >> 2, t4 = lane & 3;
#pragma unroll
    for (int mf = 0; mf < 2; mf++) {
        int r0 = row0 + wm + mf * 16 + g;
        int r1 = r0 + 8;
#pragma unroll
        for (int nf = 0; nf < 8; nf++) {
            int cb = wn + nf * 8 + t4 * 2;
            if (r0 < N_NODES)
                *(__half2*)(g_h1 + (size_t)r0 * HID + cb) =
                    __floats2half2_rn(acc[mf][nf][0], acc[mf][nf][1]);
            if (r1 < N_NODES)
                *(__half2*)(g_h1 + (size_t)r1 * HID + cb) =
                    __floats2half2_rn(acc[mf][nf][2], acc[mf][nf][3]);
        }
    }
}

// ---------------- layer-1 aggregation: a1 = dinv^2*h1_self + sum we'*h1 -----
__global__ void k_agg1() {
    int gw = (blockIdx.x * blockDim.x + threadIdx.x) >> 5;
    if (gw >= N_NODES) return;
    int lane = threadIdx.x & 31;
    const __half* hbase = g_h1;
    int doff = lane * 4;

    float4 selfv = ld_h4(hbase + (size_t)gw * HID + doff);
    float4 acc0 = make_float4(0.f, 0.f, 0.f, 0.f);
    float4 acc1 = make_float4(0.f, 0.f, 0.f, 0.f);

    int beg = g_off[gw];
    int end = beg + g_cnt[gw];
    int e = beg;
    for (; e + 2 <= end; e += 2) {
        int s0 = g_src[e], s1 = g_src[e + 1];
        float w0 = g_we[e], w1 = g_we[e + 1];
        float4 v0 = ld_h4(hbase + (size_t)s0 * HID + doff);
        float4 v1 = ld_h4(hbase + (size_t)s1 * HID + doff);
        acc0.x = fmaf(w0, v0.x, acc0.x); acc0.y = fmaf(w0, v0.y, acc0.y);
        acc0.z = fmaf(w0, v0.z, acc0.z); acc0.w = fmaf(w0, v0.w, acc0.w);
        acc1.x = fmaf(w1, v1.x, acc1.x); acc1.y = fmaf(w1, v1.y, acc1.y);
        acc1.z = fmaf(w1, v1.z, acc1.z); acc1.w = fmaf(w1, v1.w, acc1.w);
    }
    if (e < end) {
        int s0 = g_src[e];
        float w0 = g_we[e];
        float4 v0 = ld_h4(hbase + (size_t)s0 * HID + doff);
        acc0.x = fmaf(w0, v0.x, acc0.x); acc0.y = fmaf(w0, v0.y, acc0.y);
        acc0.z = fmaf(w0, v0.z, acc0.z); acc0.w = fmaf(w0, v0.w, acc0.w);
    }
    float s = g_dinv[gw];
    float s2 = s * s;
    float4 r = make_float4(fmaf(s2, selfv.x, acc0.x + acc1.x),
                           fmaf(s2, selfv.y, acc0.y + acc1.y),
                           fmaf(s2, selfv.z, acc0.z + acc1.z),
                           fmaf(s2, selfv.w, acc0.w + acc1.w));
    *(float4*)(g_a1 + (size_t)gw * HID + doff) = r;
}

// ---------------- GEMM2 via mma.sync bf16 3-term split (dinv-free) ----------
__global__ void __launch_bounds__(256) k_gemm2_mma(const float* __restrict__ b1) {
    __shared__ __align__(16) __nv_bfloat16 sAhi[128 * APAD];
    __shared__ __align__(16) __nv_bfloat16 sAlo[128 * APAD];
    __shared__ __align__(16) __nv_bfloat16 sBhi[64 * APAD];
    __shared__ __align__(16) __nv_bfloat16 sBlo[64 * APAD];
    __shared__ float b1s[HID];

    int tid = threadIdx.x;
    int lane = tid & 31;
    int wid = tid >> 5;
    int wm = (wid & 3) * 32;
    int wn = (wid >> 2) * 32;
    int row0 = blockIdx.x * 128;

    if (tid < HID) b1s[tid] = b1[tid];
    __syncthreads();

    uint32_t aHiB = smem_u32(sAhi);
    uint32_t aLoB = smem_u32(sAlo);
    uint32_t bHiB = smem_u32(sBhi);
    uint32_t bLoB = smem_u32(sBlo);

    int within = lane & 7, sub = lane >> 3;
    int aRow = within + (sub & 1) * 8;
    int aK   = (sub >> 1) * 8;
    int bN   = within + (sub >> 1) * 8;
    int bK   = (sub & 1) * 8;

    float acc[2][4][4];
#pragma unroll
    for (int mf = 0; mf < 2; mf++)
#pragma unroll
        for (int nf = 0; nf < 4; nf++)
#pragma unroll
            for (int q = 0; q < 4; q++) acc[mf][nf][q] = 0.0f;

    int fr = tid >> 1;
    int fhalf = tid & 1;
    int grow = row0 + fr;
    bool aok = grow < N_NODES;
    const float* asrc = g_a1 + (size_t)grow * HID + fhalf * 16;
    const float* bbp = b1s + fhalf * 16;

    for (int kt = 0; kt < HID; kt += 32) {
#pragma unroll
        for (int j = 0; j < 4; j++) {
            float4 v = make_float4(0.f, 0.f, 0.f, 0.f);
            if (aok) {
                v = *(const float4*)(asrc + kt + j * 4);
                v.x = fmaxf(v.x + bbp[kt + j * 4 + 0], 0.f);
                v.y = fmaxf(v.y + bbp[kt + j * 4 + 1], 0.f);
                v.z = fmaxf(v.z + bbp[kt + j * 4 + 2], 0.f);
                v.w = fmaxf(v.w + bbp[kt + j * 4 + 3], 0.f);
            }
            __nv_bfloat162 h01 = __floats2bfloat162_rn(v.x, v.y);
            __nv_bfloat162 h23 = __floats2bfloat162_rn(v.z, v.w);
            float2 f01 = __bfloat1622float2(h01);
            float2 f23 = __bfloat1622float2(h23);
            __nv_bfloat162 l01 = __floats2bfloat162_rn(v.x - f01.x, v.y - f01.y);
            __nv_bfloat162 l23 = __floats2bfloat162_rn(v.z - f23.x, v.w - f23.y);
            int eoff = fr * APAD + fhalf * 16 + j * 4;
            *(__nv_bfloat162*)&sAhi[eoff]     = h01;
            *(__nv_bfloat162*)&sAhi[eoff + 2] = h23;
            *(__nv_bfloat162*)&sAlo[eoff]     = l01;
            *(__nv_bfloat162*)&sAlo[eoff + 2] = l23;
        }
        {
            int n = tid >> 2, c8 = tid & 3;
            const __nv_bfloat16* sh = g_B2hi + (size_t)n * HID + kt + c8 * 8;
            const __nv_bfloat16* sl = g_B2lo + (size_t)n * HID + kt + c8 * 8;
            *(uint4*)&sBhi[n * APAD + c8 * 8] = *(const uint4*)sh;
            *(uint4*)&sBlo[n * APAD + c8 * 8] = *(const uint4*)sl;
        }
        __syncthreads();

#pragma unroll
        for (int kf = 0; kf < 2; kf++) {
            int kk = kf * 16;
            uint32_t ahi[2][4], alo[2][4];
#pragma unroll
            for (int mf = 0; mf < 2; mf++) {
                uint32_t off = (uint32_t)((wm + mf * 16 + aRow) * APAD + kk + aK) * 2;
                ldm4(ahi[mf], aHiB + off);
                ldm4(alo[mf], aLoB + off);
            }
#pragma unroll
            for (int np = 0; np < 2; np++) {
                uint32_t bh[4], bl[4];
                uint32_t off = (uint32_t)((wn + np * 16 + bN) * APAD + kk + bK) * 2;
                ldm4(bh, bHiB + off);
                ldm4(bl, bLoB + off);
#pragma unroll
                for (int s = 0; s < 2; s++) {
                    int nf = np * 2 + s;
#pragma unroll
                    for (int mf = 0; mf < 2; mf++) {
                        mma_bf16(acc[mf][nf], ahi[mf], bh + s * 2);
                        mma_bf16(acc[mf][nf], ahi[mf], bl + s * 2);
                        mma_bf16(acc[mf][nf], alo[mf], bh + s * 2);
                    }
                }
            }
        }
        __syncthreads();
    }

    int g = lane >> 2, t4 = lane & 3;
#pragma unroll
    for (int mf = 0; mf < 2; mf++) {
        int r0 = row0 + wm + mf * 16 + g;
        int r1 = r0 + 8;
#pragma unroll
        for (int nf = 0; nf < 4; nf++) {
            int cb = wn + nf * 8 + t4 * 2;
            if (r0 < N_NODES)
                *(__half2*)(g_h2 + (size_t)r0 * OUTD + cb) =
                    __floats2half2_rn(acc[mf][nf][0], acc[mf][nf][1]);
            if (r1 < N_NODES)
                *(__half2*)(g_h2 + (size_t)r1 * OUTD + cb) =
                    __floats2half2_rn(acc[mf][nf][2], acc[mf][nf][3]);
        }
    }
}

// ---------------- layer-2 aggregation ----------------
__global__ void k_agg2(const float* __restrict__ b2, float* __restrict__ out) {
    int gw = (blockIdx.x * blockDim.x + threadIdx.x) >> 5;
    if (gw >= N_NODES) return;
    int lane = threadIdx.x & 31;
    int doff = lane * 2;

    float2 selfv = __half22float2(*(const __half2*)(g_h2 + (size_t)gw * OUTD + doff));
    float2 acc0 = make_float2(0.f, 0.f);
    float2 acc1 = make_float2(0.f, 0.f);

    int beg = g_off[gw];
    int end = beg + g_cnt[gw];
    int e = beg;
    for (; e + 2 <= end; e += 2) {
        int s0 = g_src[e], s1 = g_src[e + 1];
        float w0 = g_we[e], w1 = g_we[e + 1];
        float2 v0 = __half22float2(*(const __half2*)(g_h2 + (size_t)s0 * OUTD + doff));
        float2 v1 = __half22float2(*(const __half2*)(g_h2 + (size_t)s1 * OUTD + doff));
        acc0.x = fmaf(w0, v0.x, acc0.x); acc0.y = fmaf(w0, v0.y, acc0.y);
        acc1.x = fmaf(w1, v1.x, acc1.x); acc1.y = fmaf(w1, v1.y, acc1.y);
    }
    if (e < end) {
        int s0 = g_src[e];
        float w0 = g_we[e];
        float2 v0 = __half22float2(*(const __half2*)(g_h2 + (size_t)s0 * OUTD + doff));
        acc0.x = fmaf(w0, v0.x, acc0.x); acc0.y = fmaf(w0, v0.y, acc0.y);
    }
    float s = g_dinv[gw];
    float s2 = s * s;
    float2 bb = ((const float2*)b2)[lane];
    float2 r = make_float2(fmaf(s2, selfv.x, acc0.x + acc1.x) + bb.x,
                           fmaf(s2, selfv.y, acc0.y + acc1.y) + bb.y);
    *(float2*)(out + (size_t)gw * OUTD + doff) = r;
}

// ---------------- launch: fork CSR build concurrent with GEMM1 ----------------
extern "C" void kernel_launch(void* const* d_in, const int* in_sizes, int n_in,
                              void* d_out, int out_size) {
    const float* x  = (const float*)d_in[0];
    const int*   ei = (const int*)d_in[1];   // int32 (JAX downgrades int64)
    const float* ew = (const float*)d_in[2];
    const float* W1 = (const float*)d_in[3];
    const float* b1 = (const float*)d_in[4];
    const float* W2 = (const float*)d_in[5];
    const float* b2 = (const float*)d_in[6];
    float*       out = (float*)d_out;

    const int* row = ei;
    const int* col = ei + N_EDGES;

    static cudaStream_t s2 = nullptr;
    static cudaEvent_t ev1 = nullptr, ev2 = nullptr;
    if (s2 == nullptr) {
        cudaStreamCreateWithFlags(&s2, cudaStreamNonBlocking);
        cudaEventCreateWithFlags(&ev1, cudaEventDisableTiming);
        cudaEventCreateWithFlags(&ev2, cudaEventDisableTiming);
    }

    k_setup<<<(N_NODES + 255) / 256, 256>>>(W1, W2);                     // 0 (main)
    cudaEventRecord(ev1, 0);
    cudaStreamWaitEvent(s2, ev1, 0);

    k_hist<<<(N_EDGES / 2 + 255) / 256, 256, 0, s2>>>(col, ew);          // 1 (s2)
    k_dinvalloc<<<(N_NODES + 255) / 256, 256, 0, s2>>>();                // 2 (s2)
    k_gemm1_mma<<<(N_NODES + 127) / 128, 256>>>(x);                      // 3 (main, concurrent)
    k_fill<<<(N_EDGES / 2 + 255) / 256, 256, 0, s2>>>(row, col, ew);     // 4 (s2)

    cudaEventRecord(ev2, s2);
    cudaStreamWaitEvent(0, ev2, 0);

    k_agg1<<<(N_NODES * 32 + 255) / 256, 256>>>();                       // 5 (main)
    k_gemm2_mma<<<(N_NODES + 127) / 128, 256>>>(b1);                     // 6 (main)
    k_agg2<<<(N_NODES * 32 + 255) / 256, 256>>>(b2, out);                // 7 (main)
}

// round 10
// speedup vs baseline: 4.3510x; 1.0960x over previous
#include <cuda_runtime.h>
#include <cuda_bf16.h>
#include <cuda_fp16.h>
#include <cstdint>

#define N_NODES 100000
#define N_EDGES 1600000
#define IN_DIM 256
#define HID 128
#define OUTD 64

// ---------------- scratch (device globals; no allocs allowed) ----------------
__device__ float g_deg[N_NODES];
__device__ float g_dinv[N_NODES];
__device__ int   g_cnt[N_NODES];
__device__ int   g_off[N_NODES];
__device__ int   g_cur[N_NODES];
__device__ int   g_total;
__device__ int2  g_edge[N_EDGES];   // {src, float_bits(w * dinv[col] * dinv[row])}
__device__ __nv_bfloat16 g_B1hi[HID * IN_DIM];  // W1 split, [n][k]
__device__ __nv_bfloat16 g_B1lo[HID * IN_DIM];
__device__ __nv_bfloat16 g_B2hi[OUTD * HID];    // W2 split, [n][k]
__device__ __nv_bfloat16 g_B2lo[OUTD * HID];
__device__ __half g_h1[(size_t)N_NODES * HID];  // fp16: x @ W1 (unscaled)
__device__ __half g_a1[(size_t)N_NODES * HID];  // fp16: relu(agg + b1)
__device__ __half g_h2[(size_t)N_NODES * OUTD]; // fp16: a1relu @ W2 (unscaled)

__device__ __forceinline__ uint32_t smem_u32(const void* p) {
    uint32_t a;
    asm("{ .reg .u64 t; cvta.to.shared.u64 t, %1; cvt.u32.u64 %0, t; }" : "=r"(a) : "l"(p));
    return a;
}
__device__ __forceinline__ void ldm4(uint32_t* r, uint32_t addr) {
    asm volatile("ldmatrix.sync.aligned.m8n8.x4.shared.b16 {%0,%1,%2,%3}, [%4];"
                 : "=r"(r[0]), "=r"(r[1]), "=r"(r[2]), "=r"(r[3]) : "r"(addr));
}
__device__ __forceinline__ void mma_bf16(float* d, const uint32_t* a, const uint32_t* b) {
    asm volatile(
        "mma.sync.aligned.m16n8k16.row.col.f32.bf16.bf16.f32 "
        "{%0,%1,%2,%3}, {%4,%5,%6,%7}, {%8,%9}, {%0,%1,%2,%3};"
        : "+f"(d[0]), "+f"(d[1]), "+f"(d[2]), "+f"(d[3])
        : "r"(a[0]), "r"(a[1]), "r"(a[2]), "r"(a[3]), "r"(b[0]), "r"(b[1]));
}
__device__ __forceinline__ float4 ld_h4(const __half* p) {
    uint2 u = *(const uint2*)p;
    __half2 a = *(__half2*)&u.x, b = *(__half2*)&u.y;
    float2 fa = __half22float2(a), fb = __half22float2(b);
    return make_float4(fa.x, fa.y, fb.x, fb.y);
}
__device__ __forceinline__ void cp_async16(void* smem, const void* gmem) {
    unsigned s = (unsigned)__cvta_generic_to_shared(smem);
    asm volatile("cp.async.cg.shared.global [%0], [%1], 16;" :: "r"(s), "l"(gmem));
}
#define CP_COMMIT() asm volatile("cp.async.commit_group;")
#define CP_WAIT0()  asm volatile("cp.async.wait_group 0;")

// ---------------- fused setup ----------------
__global__ void k_setup(const float* __restrict__ W1, const float* __restrict__ W2) {
    int i = blockIdx.x * blockDim.x + threadIdx.x;
    if (i < N_NODES) { g_deg[i] = 1.0f; g_cnt[i] = 0; }
    if (i == 0) g_total = 0;
    if (i < HID * IN_DIM) {
        int n = i >> 8, k = i & 255;
        float w = W1[(size_t)k * HID + n];
        __nv_bfloat16 h = __float2bfloat16(w);
        g_B1hi[i] = h;
        g_B1lo[i] = __float2bfloat16(w - __bfloat162float(h));
    }
    if (i < OUTD * HID) {
        int n = i >> 7, k = i & 127;
        float w = W2[(size_t)k * OUTD + n];
        __nv_bfloat16 h = __float2bfloat16(w);
        g_B2hi[i] = h;
        g_B2lo[i] = __float2bfloat16(w - __bfloat162float(h));
    }
}

// ---------------- histogram: 2 edges per thread ----------------
__global__ void k_hist(const int* __restrict__ col, const float* __restrict__ w) {
    int e = (blockIdx.x * blockDim.x + threadIdx.x) * 2;
    if (e + 1 < N_EDGES) {
        int2 c = *(const int2*)(col + e);
        float2 ww = *(const float2*)(w + e);
        atomicAdd(&g_deg[c.x], ww.x);
        atomicAdd(&g_cnt[c.x], 1);
        atomicAdd(&g_deg[c.y], ww.y);
        atomicAdd(&g_cnt[c.y], 1);
    } else if (e < N_EDGES) {
        atomicAdd(&g_deg[col[e]], w[e]);
        atomicAdd(&g_cnt[col[e]], 1);
    }
}

// ---------------- fused dinv + CSR bucket allocation ----------------
__global__ void __launch_bounds__(256) k_dinvalloc() {
    __shared__ int sc[256];
    __shared__ int sbase;
    int tid = threadIdx.x;
    int i = blockIdx.x * 256 + tid;
    if (i < N_NODES) {
        float d = g_deg[i];
        g_dinv[i] = d > 0.0f ? rsqrtf(d) : 0.0f;
    }
    int v = (i < N_NODES) ? g_cnt[i] : 0;
    sc[tid] = v;
    __syncthreads();
#pragma unroll
    for (int off = 1; off < 256; off <<= 1) {
        int t = (tid >= off) ? sc[tid - off] : 0;
        __syncthreads();
        sc[tid] += t;
        __syncthreads();
    }
    if (tid == 255) sbase = atomicAdd(&g_total, sc[255]);
    __syncthreads();
    if (i < N_NODES) {
        int base = sbase + sc[tid] - v;
        g_off[i] = base;
        g_cur[i] = base;
    }
}

// ---------------- CSR fill: packed int2 payload ----------------
__global__ void k_fill(const int* __restrict__ row, const int* __restrict__ col,
                       const float* __restrict__ w) {
    int e = (blockIdx.x * blockDim.x + threadIdx.x) * 2;
    if (e + 1 < N_EDGES) {
        int2 r = *(const int2*)(row + e);
        int2 c = *(const int2*)(col + e);
        float2 ww = *(const float2*)(w + e);
        float w0 = ww.x * g_dinv[c.x] * g_dinv[r.x];
        float w1 = ww.y * g_dinv[c.y] * g_dinv[r.y];
        int p0 = atomicAdd(&g_cur[c.x], 1);
        g_edge[p0] = make_int2(r.x, __float_as_int(w0));
        int p1 = atomicAdd(&g_cur[c.y], 1);
        g_edge[p1] = make_int2(r.y, __float_as_int(w1));
    } else if (e < N_EDGES) {
        float w0 = w[e] * g_dinv[col[e]] * g_dinv[row[e]];
        int pos = atomicAdd(&g_cur[col[e]], 1);
        g_edge[pos] = make_int2(row[e], __float_as_int(w0));
    }
}

// ---------------- GEMM1: 2-stage double-buffered bf16-split HMMA ----------
#define APAD 40
#define TILE_B (128 * APAD * 2)          // 10240 bytes per tile
#define SMEM_G1 (8 * TILE_B)             // 81920 bytes
__global__ void __launch_bounds__(256, 2) k_gemm1_mma(const float* __restrict__ x) {
    extern __shared__ __align__(16) char dsm[];
    // stage layout: [stage][Ahi, Alo, Bhi, Blo]
    auto tileP = [&](int stage, int which) -> __nv_bfloat16* {
        return (__nv_bfloat16*)(dsm + (size_t)stage * 4 * TILE_B + which * TILE_B);
    };

    int tid = threadIdx.x;
    int lane = tid & 31;
    int wid = tid >> 5;
    int wm = (wid & 3) * 32;
    int wn = (wid >> 2) * 64;
    int row0 = blockIdx.x * 128;

    int within = lane & 7, sub = lane >> 3;
    int aRow = within + (sub & 1) * 8;
    int aK   = (sub >> 1) * 8;
    int bN   = within + (sub >> 1) * 8;
    int bK   = (sub & 1) * 8;

    float acc[2][8][4];
#pragma unroll
    for (int mf = 0; mf < 2; mf++)
#pragma unroll
        for (int nf = 0; nf < 8; nf++)
#pragma unroll
            for (int q = 0; q < 4; q++) acc[mf][nf][q] = 0.0f;

    int fr = tid >> 1;
    int fhalf = tid & 1;
    int grow = row0 + fr;
    bool aok = grow < N_NODES;
    const float* asrc = x + (size_t)grow * IN_DIM + fhalf * 16;
    const float4 z4 = make_float4(0.f, 0.f, 0.f, 0.f);

    int bn0 = tid >> 2, bc0 = (tid & 3) * 8;
    int bn1 = (tid + 256) >> 2;

    auto issueB = [&](int kt, int stage) {
        __nv_bfloat16* bh = tileP(stage, 2);
        __nv_bfloat16* bl = tileP(stage, 3);
        cp_async16(bh + bn0 * APAD + bc0, g_B1hi + (size_t)bn0 * IN_DIM + kt + bc0);
        cp_async16(bl + bn0 * APAD + bc0, g_B1lo + (size_t)bn0 * IN_DIM + kt + bc0);
        cp_async16(bh + bn1 * APAD + bc0, g_B1hi + (size_t)bn1 * IN_DIM + kt + bc0);
        cp_async16(bl + bn1 * APAD + bc0, g_B1lo + (size_t)bn1 * IN_DIM + kt + bc0);
        CP_COMMIT();
    };
    auto storeA = [&](const float4* ra, int stage) {
        __nv_bfloat16* ah = tileP(stage, 0);
        __nv_bfloat16* al = tileP(stage, 1);
#pragma unroll
        for (int j = 0; j < 4; j++) {
            float4 v = ra[j];
            __nv_bfloat162 h01 = __floats2bfloat162_rn(v.x, v.y);
            __nv_bfloat162 h23 = __floats2bfloat162_rn(v.z, v.w);
            float2 f01 = __bfloat1622float2(h01);
            float2 f23 = __bfloat1622float2(h23);
            __nv_bfloat162 l01 = __floats2bfloat162_rn(v.x - f01.x, v.y - f01.y);
            __nv_bfloat162 l23 = __floats2bfloat162_rn(v.z - f23.x, v.w - f23.y);
            int eoff = fr * APAD + fhalf * 16 + j * 4;
            *(__nv_bfloat162*)(ah + eoff)     = h01;
            *(__nv_bfloat162*)(ah + eoff + 2) = h23;
            *(__nv_bfloat162*)(al + eoff)     = l01;
            *(__nv_bfloat162*)(al + eoff + 2) = l23;
        }
    };

    // prologue: fill stage 0, prefetch A(1)
    float4 ra[4];
#pragma unroll
    for (int j = 0; j < 4; j++) ra[j] = aok ? *(const float4*)(asrc + j * 4) : z4;
    issueB(0, 0);
    storeA(ra, 0);
#pragma unroll
    for (int j = 0; j < 4; j++) ra[j] = aok ? *(const float4*)(asrc + 32 + j * 4) : z4;
    CP_WAIT0();
    __syncthreads();

#pragma unroll 1
    for (int t = 0; t < 8; t++) {
        int cur = t & 1, nxt = cur ^ 1;
        if (t < 7) {
            issueB((t + 1) * 32, nxt);
            storeA(ra, nxt);
            if (t < 6) {
#pragma unroll
                for (int j = 0; j < 4; j++)
                    ra[j] = aok ? *(const float4*)(asrc + (t + 2) * 32 + j * 4) : z4;
            }
        }
        uint32_t aHiB = smem_u32(tileP(cur, 0));
        uint32_t aLoB = smem_u32(tileP(cur, 1));
        uint32_t bHiB = smem_u32(tileP(cur, 2));
        uint32_t bLoB = smem_u32(tileP(cur, 3));
#pragma unroll
        for (int kf = 0; kf < 2; kf++) {
            int kk = kf * 16;
            uint32_t ahi[2][4], alo[2][4];
#pragma unroll
            for (int mf = 0; mf < 2; mf++) {
                uint32_t off = (uint32_t)((wm + mf * 16 + aRow) * APAD + kk + aK) * 2;
                ldm4(ahi[mf], aHiB + off);
                ldm4(alo[mf], aLoB + off);
            }
#pragma unroll
            for (int np = 0; np < 4; np++) {
                uint32_t bh[4], bl[4];
                uint32_t off = (uint32_t)((wn + np * 16 + bN) * APAD + kk + bK) * 2;
                ldm4(bh, bHiB + off);
                ldm4(bl, bLoB + off);
#pragma unroll
                for (int s = 0; s < 2; s++) {
                    int nf = np * 2 + s;
#pragma unroll
                    for (int mf = 0; mf < 2; mf++) {
                        mma_bf16(acc[mf][nf], ahi[mf], bh + s * 2);
                        mma_bf16(acc[mf][nf], ahi[mf], bl + s * 2);
                        mma_bf16(acc[mf][nf], alo[mf], bh + s * 2);
                    }
                }
            }
        }
        if (t < 7) {
            CP_WAIT0();
            __syncthreads();
        }
    }

    // epilogue: g_h1 (fp16) = C (unscaled)
    int g = lane >> 2, t4 = lane & 3;
#pragma unroll
    for (int mf = 0; mf < 2; mf++) {
        int r0 = row0 + wm + mf * 16 + g;
        int r1 = r0 + 8;
#pragma unroll
        for (int nf = 0; nf < 8; nf++) {
            int cb = wn + nf * 8 + t4 * 2;
            if (r0 < N_NODES)
                *(__half2*)(g_h1 + (size_t)r0 * HID + cb) =
                    __floats2half2_rn(acc[mf][nf][0], acc[mf][nf][1]);
            if (r1 < N_NODES)
                *(__half2*)(g_h1 + (size_t)r1 * HID + cb) =
                    __floats2half2_rn(acc[mf][nf][2], acc[mf][nf][3]);
        }
    }
}

// ---------------- layer-1 aggregation + bias + relu -> fp16 a1 ----------------
__global__ void k_agg1(const float* __restrict__ b1) {
    int gw = (blockIdx.x * blockDim.x + threadIdx.x) >> 5;
    if (gw >= N_NODES) return;
    int lane = threadIdx.x & 31;
    const __half* hbase = g_h1;
    int doff = lane * 4;

    float4 selfv = ld_h4(hbase + (size_t)gw * HID + doff);
    float4 acc0 = make_float4(0.f, 0.f, 0.f, 0.f);
    float4 acc1 = make_float4(0.f, 0.f, 0.f, 0.f);

    int beg = g_off[gw];
    int end = beg + g_cnt[gw];
    int e = beg;
    for (; e + 2 <= end; e += 2) {
        int2 e0 = g_edge[e];
        int2 e1 = g_edge[e + 1];
        float w0 = __int_as_float(e0.y), w1 = __int_as_float(e1.y);
        float4 v0 = ld_h4(hbase + (size_t)e0.x * HID + doff);
        float4 v1 = ld_h4(hbase + (size_t)e1.x * HID + doff);
        acc0.x = fmaf(w0, v0.x, acc0.x); acc0.y = fmaf(w0, v0.y, acc0.y);
        acc0.z = fmaf(w0, v0.z, acc0.z); acc0.w = fmaf(w0, v0.w, acc0.w);
        acc1.x = fmaf(w1, v1.x, acc1.x); acc1.y = fmaf(w1, v1.y, acc1.y);
        acc1.z = fmaf(w1, v1.z, acc1.z); acc1.w = fmaf(w1, v1.w, acc1.w);
    }
    if (e < end) {
        int2 e0 = g_edge[e];
        float w0 = __int_as_float(e0.y);
        float4 v0 = ld_h4(hbase + (size_t)e0.x * HID + doff);
        acc0.x = fmaf(w0, v0.x, acc0.x); acc0.y = fmaf(w0, v0.y, acc0.y);
        acc0.z = fmaf(w0, v0.z, acc0.z); acc0.w = fmaf(w0, v0.w, acc0.w);
    }
    float s = g_dinv[gw];
    float s2 = s * s;
    float4 bb = *(const float4*)(b1 + doff);
    float rx = fmaxf(fmaf(s2, selfv.x, acc0.x + acc1.x) + bb.x, 0.f);
    float ry = fmaxf(fmaf(s2, selfv.y, acc0.y + acc1.y) + bb.y, 0.f);
    float rz = fmaxf(fmaf(s2, selfv.z, acc0.z + acc1.z) + bb.z, 0.f);
    float rw = fmaxf(fmaf(s2, selfv.w, acc0.w + acc1.w) + bb.w, 0.f);
    __half2 h0 = __floats2half2_rn(rx, ry);
    __half2 h1v = __floats2half2_rn(rz, rw);
    *(__half2*)(g_a1 + (size_t)gw * HID + doff)     = h0;
    *(__half2*)(g_a1 + (size_t)gw * HID + doff + 2) = h1v;
}

// ---------------- GEMM2: a1(fp16) @ W2, bf16 3-term split ----------------
__global__ void __launch_bounds__(256) k_gemm2_mma() {
    __shared__ __align__(16) __nv_bfloat16 sAhi[128 * APAD];
    __shared__ __align__(16) __nv_bfloat16 sAlo[128 * APAD];
    __shared__ __align__(16) __nv_bfloat16 sBhi[64 * APAD];
    __shared__ __align__(16) __nv_bfloat16 sBlo[64 * APAD];

    int tid = threadIdx.x;
    int lane = tid & 31;
    int wid = tid >> 5;
    int wm = (wid & 3) * 32;
    int wn = (wid >> 2) * 32;
    int row0 = blockIdx.x * 128;

    uint32_t aHiB = smem_u32(sAhi);
    uint32_t aLoB = smem_u32(sAlo);
    uint32_t bHiB = smem_u32(sBhi);
    uint32_t bLoB = smem_u32(sBlo);

    int within = lane & 7, sub = lane >> 3;
    int aRow = within + (sub & 1) * 8;
    int aK   = (sub >> 1) * 8;
    int bN   = within + (sub >> 1) * 8;
    int bK   = (sub & 1) * 8;

    float acc[2][4][4];
#pragma unroll
    for (int mf = 0; mf < 2; mf++)
#pragma unroll
        for (int nf = 0; nf < 4; nf++)
#pragma unroll
            for (int q = 0; q < 4; q++) acc[mf][nf][q] = 0.0f;

    int fr = tid >> 1;
    int fhalf = tid & 1;
    int grow = row0 + fr;
    bool aok = grow < N_NODES;
    const __half* asrc = g_a1 + (size_t)grow * HID + fhalf * 16;

    for (int kt = 0; kt < HID; kt += 32) {
#pragma unroll
        for (int j = 0; j < 4; j++) {
            float4 v = make_float4(0.f, 0.f, 0.f, 0.f);
            if (aok) v = ld_h4(asrc + kt + j * 4);
            __nv_bfloat162 h01 = __floats2bfloat162_rn(v.x, v.y);
            __nv_bfloat162 h23 = __floats2bfloat162_rn(v.z, v.w);
            float2 f01 = __bfloat1622float2(h01);
            float2 f23 = __bfloat1622float2(h23);
            __nv_bfloat162 l01 = __floats2bfloat162_rn(v.x - f01.x, v.y - f01.y);
            __nv_bfloat162 l23 = __floats2bfloat162_rn(v.z - f23.x, v.w - f23.y);
            int eoff = fr * APAD + fhalf * 16 + j * 4;
            *(__nv_bfloat162*)&sAhi[eoff]     = h01;
            *(__nv_bfloat162*)&sAhi[eoff + 2] = h23;
            *(__nv_bfloat162*)&sAlo[eoff]     = l01;
            *(__nv_bfloat162*)&sAlo[eoff + 2] = l23;
        }
        {
            int n = tid >> 2, c8 = tid & 3;
            const __nv_bfloat16* sh = g_B2hi + (size_t)n * HID + kt + c8 * 8;
            const __nv_bfloat16* sl = g_B2lo + (size_t)n * HID + kt + c8 * 8;
            *(uint4*)&sBhi[n * APAD + c8 * 8] = *(const uint4*)sh;
            *(uint4*)&sBlo[n * APAD + c8 * 8] = *(const uint4*)sl;
        }
        __syncthreads();

#pragma unroll
        for (int kf = 0; kf < 2; kf++) {
            int kk = kf * 16;
            uint32_t ahi[2][4], alo[2][4];
#pragma unroll
            for (int mf = 0; mf < 2; mf++) {
                uint32_t off = (uint32_t)((wm + mf * 16 + aRow) * APAD + kk + aK) * 2;
                ldm4(ahi[mf], aHiB + off);
                ldm4(alo[mf], aLoB + off);
            }
#pragma unroll
            for (int np = 0; np < 2; np++) {
                uint32_t bh[4], bl[4];
                uint32_t off = (uint32_t)((wn + np * 16 + bN) * APAD + kk + bK) * 2;
                ldm4(bh, bHiB + off);
                ldm4(bl, bLoB + off);
#pragma unroll
                for (int s = 0; s < 2; s++) {
                    int nf = np * 2 + s;
#pragma unroll
                    for (int mf = 0; mf < 2; mf++) {
                        mma_bf16(acc[mf][nf], ahi[mf], bh + s * 2);
                        mma_bf16(acc[mf][nf], ahi[mf], bl + s * 2);
                        mma_bf16(acc[mf][nf], alo[mf], bh + s * 2);
                    }
                }
            }
        }
        __syncthreads();
    }

    int g = lane >> 2, t4 = lane & 3;
#pragma unroll
    for (int mf = 0; mf < 2; mf++) {
        int r0 = row0 + wm + mf * 16 + g;
        int r1 = r0 + 8;
#pragma unroll
        for (int nf = 0; nf < 4; nf++) {
            int cb = wn + nf * 8 + t4 * 2;
            if (r0 < N_NODES)
                *(__half2*)(g_h2 + (size_t)r0 * OUTD + cb) =
                    __floats2half2_rn(acc[mf][nf][0], acc[mf][nf][1]);
            if (r1 < N_NODES)
                *(__half2*)(g_h2 + (size_t)r1 * OUTD + cb) =
                    __floats2half2_rn(acc[mf][nf][2], acc[mf][nf][3]);
        }
    }
}

// ---------------- layer-2 aggregation ----------------
__global__ void k_agg2(const float* __restrict__ b2, float* __restrict__ out) {
    int gw = (blockIdx.x * blockDim.x + threadIdx.x) >> 5;
    if (gw >= N_NODES) return;
    int lane = threadIdx.x & 31;
    int doff = lane * 2;

    float2 selfv = __half22float2(*(const __half2*)(g_h2 + (size_t)gw * OUTD + doff));
    float2 acc0 = make_float2(0.f, 0.f);
    float2 acc1 = make_float2(0.f, 0.f);

    int beg = g_off[gw];
    int end = beg + g_cnt[gw];
    int e = beg;
    for (; e + 2 <= end; e += 2) {
        int2 e0 = g_edge[e];
        int2 e1 = g_edge[e + 1];
        float w0 = __int_as_float(e0.y), w1 = __int_as_float(e1.y);
        float2 v0 = __half22float2(*(const __half2*)(g_h2 + (size_t)e0.x * OUTD + doff));
        float2 v1 = __half22float2(*(const __half2*)(g_h2 + (size_t)e1.x * OUTD + doff));
        acc0.x = fmaf(w0, v0.x, acc0.x); acc0.y = fmaf(w0, v0.y, acc0.y);
        acc1.x = fmaf(w1, v1.x, acc1.x); acc1.y = fmaf(w1, v1.y, acc1.y);
    }
    if (e < end) {
        int2 e0 = g_edge[e];
        float w0 = __int_as_float(e0.y);
        float2 v0 = __half22float2(*(const __half2*)(g_h2 + (size_t)e0.x * OUTD + doff));
        acc0.x = fmaf(w0, v0.x, acc0.x); acc0.y = fmaf(w0, v0.y, acc0.y);
    }
    float s = g_dinv[gw];
    float s2 = s * s;
    float2 bb = ((const float2*)b2)[lane];
    float2 r = make_float2(fmaf(s2, selfv.x, acc0.x + acc1.x) + bb.x,
                           fmaf(s2, selfv.y, acc0.y + acc1.y) + bb.y);
    *(float2*)(out + (size_t)gw * OUTD + doff) = r;
}

// ---------------- launch ----------------
extern "C" void kernel_launch(void* const* d_in, const int* in_sizes, int n_in,
                              void* d_out, int out_size) {
    const float* x  = (const float*)d_in[0];
    const int*   ei = (const int*)d_in[1];   // int32 (JAX downgrades int64)
    const float* ew = (const float*)d_in[2];
    const float* W1 = (const float*)d_in[3];
    const float* b1 = (const float*)d_in[4];
    const float* W2 = (const float*)d_in[5];
    const float* b2 = (const float*)d_in[6];
    float*       out = (float*)d_out;

    const int* row = ei;
    const int* col = ei + N_EDGES;

    static cudaStream_t s2 = nullptr;
    static cudaEvent_t ev1 = nullptr, ev2 = nullptr;
    if (s2 == nullptr) {
        cudaStreamCreateWithFlags(&s2, cudaStreamNonBlocking);
        cudaEventCreateWithFlags(&ev1, cudaEventDisableTiming);
        cudaEventCreateWithFlags(&ev2, cudaEventDisableTiming);
        cudaFuncSetAttribute(k_gemm1_mma, cudaFuncAttributeMaxDynamicSharedMemorySize, SMEM_G1);
    }

    k_setup<<<(N_NODES + 255) / 256, 256>>>(W1, W2);                     // 1 (main)
    cudaEventRecord(ev1, 0);
    cudaStreamWaitEvent(s2, ev1, 0);

    k_hist<<<(N_EDGES / 2 + 255) / 256, 256, 0, s2>>>(col, ew);          // 2 (s2)
    k_dinvalloc<<<(N_NODES + 255) / 256, 256, 0, s2>>>();                // 3 (s2)
    k_gemm1_mma<<<(N_NODES + 127) / 128, 256, SMEM_G1>>>(x);             // 4 (main, profiled)
    k_fill<<<(N_EDGES / 2 + 255) / 256, 256, 0, s2>>>(row, col, ew);     // 5 (s2)

    cudaEventRecord(ev2, s2);
    cudaStreamWaitEvent(0, ev2, 0);

    k_agg1<<<(N_NODES * 32 + 255) / 256, 256>>>(b1);                     // 6 (main)
    k_gemm2_mma<<<(N_NODES + 127) / 128, 256>>>();                       // 7 (main)
    k_agg2<<<(N_NODES * 32 + 255) / 256, 256>>>(b2, out);                // 8 (main)
}

// round 12
// speedup vs baseline: 5.0571x; 1.1623x over previous
#include <cuda_runtime.h>
#include <cuda_fp16.h>
#include <cstdint>

#define N_NODES 100000
#define N_EDGES 1600000
#define IN_DIM 256
#define HID 128
#define OUTD 64

// ---------------- scratch (device globals; no allocs allowed) ----------------
__device__ float g_deg[N_NODES];
__device__ float g_dinv[N_NODES];
__device__ int   g_cnt[N_NODES];
__device__ int   g_off[N_NODES];
__device__ int   g_cur[N_NODES];
__device__ int   g_total;
__device__ int2  g_edge[N_EDGES];   // {src, float_bits(w * dinv[col] * dinv[row])}
__device__ __half g_W1h[HID * IN_DIM];   // W1 fp16, [n][k]
__device__ __half g_W2h[OUTD * HID];     // W2 fp16, [n][k]
__device__ __half g_h1[(size_t)N_NODES * HID];  // fp16: x @ W1 (unscaled)
__device__ __half g_a1[(size_t)N_NODES * HID];  // fp16: relu(agg + b1)
__device__ __half g_h2[(size_t)N_NODES * OUTD]; // fp16: a1 @ W2 (unscaled)

__device__ __forceinline__ uint32_t smem_u32(const void* p) {
    uint32_t a;
    asm("{ .reg .u64 t; cvta.to.shared.u64 t, %1; cvt.u32.u64 %0, t; }" : "=r"(a) : "l"(p));
    return a;
}
__device__ __forceinline__ void ldm4(uint32_t* r, uint32_t addr) {
    asm volatile("ldmatrix.sync.aligned.m8n8.x4.shared.b16 {%0,%1,%2,%3}, [%4];"
                 : "=r"(r[0]), "=r"(r[1]), "=r"(r[2]), "=r"(r[3]) : "r"(addr));
}
__device__ __forceinline__ void mma_f16(float* d, const uint32_t* a, const uint32_t* b) {
    asm volatile(
        "mma.sync.aligned.m16n8k16.row.col.f32.f16.f16.f32 "
        "{%0,%1,%2,%3}, {%4,%5,%6,%7}, {%8,%9}, {%0,%1,%2,%3};"
        : "+f"(d[0]), "+f"(d[1]), "+f"(d[2]), "+f"(d[3])
        : "r"(a[0]), "r"(a[1]), "r"(a[2]), "r"(a[3]), "r"(b[0]), "r"(b[1]));
}
__device__ __forceinline__ float4 ld_h4(const __half* p) {
    uint2 u = *(const uint2*)p;
    __half2 a = *(__half2*)&u.x, b = *(__half2*)&u.y;
    float2 fa = __half22float2(a), fb = __half22float2(b);
    return make_float4(fa.x, fa.y, fb.x, fb.y);
}
__device__ __forceinline__ void cp_async16(void* smem, const void* gmem) {
    unsigned s = (unsigned)__cvta_generic_to_shared(smem);
    asm volatile("cp.async.cg.shared.global [%0], [%1], 16;" :: "r"(s), "l"(gmem));
}
#define CP_COMMIT() asm volatile("cp.async.commit_group;")
#define CP_WAIT(n)  asm volatile("cp.async.wait_group %0;" :: "n"(n))

// ---------------- fused setup ----------------
__global__ void k_setup(const float* __restrict__ W1, const float* __restrict__ W2) {
    int i = blockIdx.x * blockDim.x + threadIdx.x;
    if (i < N_NODES) { g_deg[i] = 1.0f; g_cnt[i] = 0; }
    if (i == 0) g_total = 0;
    if (i < HID * IN_DIM) {              // W1: [k][n] f32 -> [n][k] fp16
        int n = i >> 8, k = i & 255;
        g_W1h[i] = __float2half(W1[(size_t)k * HID + n]);
    }
    if (i < OUTD * HID) {                // W2: [k][n] f32 -> [n][k] fp16
        int n = i >> 7, k = i & 127;
        g_W2h[i] = __float2half(W2[(size_t)k * OUTD + n]);
    }
}

// ---------------- histogram: 2 edges per thread ----------------
__global__ void k_hist(const int* __restrict__ col, const float* __restrict__ w) {
    int e = (blockIdx.x * blockDim.x + threadIdx.x) * 2;
    if (e + 1 < N_EDGES) {
        int2 c = *(const int2*)(col + e);
        float2 ww = *(const float2*)(w + e);
        atomicAdd(&g_deg[c.x], ww.x);
        atomicAdd(&g_cnt[c.x], 1);
        atomicAdd(&g_deg[c.y], ww.y);
        atomicAdd(&g_cnt[c.y], 1);
    } else if (e < N_EDGES) {
        atomicAdd(&g_deg[col[e]], w[e]);
        atomicAdd(&g_cnt[col[e]], 1);
    }
}

// ---------------- fused dinv + CSR bucket allocation ----------------
__global__ void __launch_bounds__(256) k_dinvalloc() {
    __shared__ int sc[256];
    __shared__ int sbase;
    int tid = threadIdx.x;
    int i = blockIdx.x * 256 + tid;
    if (i < N_NODES) {
        float d = g_deg[i];
        g_dinv[i] = d > 0.0f ? rsqrtf(d) : 0.0f;
    }
    int v = (i < N_NODES) ? g_cnt[i] : 0;
    sc[tid] = v;
    __syncthreads();
#pragma unroll
    for (int off = 1; off < 256; off <<= 1) {
        int t = (tid >= off) ? sc[tid - off] : 0;
        __syncthreads();
        sc[tid] += t;
        __syncthreads();
    }
    if (tid == 255) sbase = atomicAdd(&g_total, sc[255]);
    __syncthreads();
    if (i < N_NODES) {
        int base = sbase + sc[tid] - v;
        g_off[i] = base;
        g_cur[i] = base;
    }
}

// ---------------- CSR fill: packed int2 payload ----------------
__global__ void k_fill(const int* __restrict__ row, const int* __restrict__ col,
                       const float* __restrict__ w) {
    int e = (blockIdx.x * blockDim.x + threadIdx.x) * 2;
    if (e + 1 < N_EDGES) {
        int2 r = *(const int2*)(row + e);
        int2 c = *(const int2*)(col + e);
        float2 ww = *(const float2*)(w + e);
        float w0 = ww.x * g_dinv[c.x] * g_dinv[r.x];
        float w1 = ww.y * g_dinv[c.y] * g_dinv[r.y];
        int p0 = atomicAdd(&g_cur[c.x], 1);
        g_edge[p0] = make_int2(r.x, __float_as_int(w0));
        int p1 = atomicAdd(&g_cur[c.y], 1);
        g_edge[p1] = make_int2(r.y, __float_as_int(w1));
    } else if (e < N_EDGES) {
        float w0 = w[e] * g_dinv[col[e]] * g_dinv[row[e]];
        int pos = atomicAdd(&g_cur[col[e]], 1);
        g_edge[pos] = make_int2(row[e], __float_as_int(w0));
    }
}

// ---------------- GEMM1: fp16 HMMA, 2-stage double buffer ----------------
// C[100000,128] = x @ W1; BM=128 BN=128 BK=32, 256 thr (8 warps 4x2).
#define APAD 40
__global__ void __launch_bounds__(256, 2) k_gemm1_mma(const float* __restrict__ x) {
    __shared__ __align__(16) __half sA[2][128 * APAD];
    __shared__ __align__(16) __half sB[2][128 * APAD];

    int tid = threadIdx.x;
    int lane = tid & 31;
    int wid = tid >> 5;
    int wm = (wid & 3) * 32;
    int wn = (wid >> 2) * 64;
    int row0 = blockIdx.x * 128;

    int within = lane & 7, sub = lane >> 3;
    int aRow = within + (sub & 1) * 8;
    int aK   = (sub >> 1) * 8;
    int bN   = within + (sub >> 1) * 8;
    int bK   = (sub & 1) * 8;

    float acc[2][8][4];
#pragma unroll
    for (int mf = 0; mf < 2; mf++)
#pragma unroll
        for (int nf = 0; nf < 8; nf++)
#pragma unroll
            for (int q = 0; q < 4; q++) acc[mf][nf][q] = 0.0f;

    int fr = tid >> 1;
    int fhalf = tid & 1;
    int grow = row0 + fr;
    bool aok = grow < N_NODES;
    const float* asrc = x + (size_t)grow * IN_DIM + fhalf * 16;
    const float4 z4 = make_float4(0.f, 0.f, 0.f, 0.f);

    // B tile: 128 n-rows x 32 k halves = 512 16B-chunks, 2 per thread
    auto issueB = [&](int kt, int stage) {
#pragma unroll
        for (int j = 0; j < 2; j++) {
            int i = tid + j * 256;           // 0..511
            int n = i >> 2, c8 = (i & 3) * 8;
            cp_async16(&sB[stage][n * APAD + c8], g_W1h + (size_t)n * IN_DIM + kt + c8);
        }
        CP_COMMIT();
    };
    auto storeA = [&](const float4* ra, int stage) {
#pragma unroll
        for (int j = 0; j < 4; j++) {
            float4 v = ra[j];
            __half2 h01 = __floats2half2_rn(v.x, v.y);
            __half2 h23 = __floats2half2_rn(v.z, v.w);
            int eoff = fr * APAD + fhalf * 16 + j * 4;
            *(__half2*)&sA[stage][eoff]     = h01;
            *(__half2*)&sA[stage][eoff + 2] = h23;
        }
    };

    float4 ra[4];
#pragma unroll
    for (int j = 0; j < 4; j++) ra[j] = aok ? *(const float4*)(asrc + j * 4) : z4;
    issueB(0, 0);
    storeA(ra, 0);
#pragma unroll
    for (int j = 0; j < 4; j++) ra[j] = aok ? *(const float4*)(asrc + 32 + j * 4) : z4;
    CP_WAIT(0);
    __syncthreads();

#pragma unroll 1
    for (int t = 0; t < 8; t++) {
        int cur = t & 1, nxt = cur ^ 1;
        if (t < 7) {
            issueB((t + 1) * 32, nxt);
            storeA(ra, nxt);
            if (t < 6) {
#pragma unroll
                for (int j = 0; j < 4; j++)
                    ra[j] = aok ? *(const float4*)(asrc + (t + 2) * 32 + j * 4) : z4;
            }
        }
        uint32_t aB = smem_u32(sA[cur]);
        uint32_t bB = smem_u32(sB[cur]);
#pragma unroll
        for (int kf = 0; kf < 2; kf++) {
            int kk = kf * 16;
            uint32_t af[2][4];
#pragma unroll
            for (int mf = 0; mf < 2; mf++)
                ldm4(af[mf], aB + (uint32_t)((wm + mf * 16 + aRow) * APAD + kk + aK) * 2);
#pragma unroll
            for (int np = 0; np < 4; np++) {
                uint32_t bf[4];
                ldm4(bf, bB + (uint32_t)((wn + np * 16 + bN) * APAD + kk + bK) * 2);
#pragma unroll
                for (int s = 0; s < 2; s++) {
                    int nf = np * 2 + s;
#pragma unroll
                    for (int mf = 0; mf < 2; mf++)
                        mma_f16(acc[mf][nf], af[mf], bf + s * 2);
                }
            }
        }
        if (t < 7) {
            CP_WAIT(0);
            __syncthreads();
        }
    }

    // epilogue: g_h1 (fp16) = C (unscaled)
    int g = lane >> 2, t4 = lane & 3;
#pragma unroll
    for (int mf = 0; mf < 2; mf++) {
        int r0 = row0 + wm + mf * 16 + g;
        int r1 = r0 + 8;
#pragma unroll
        for (int nf = 0; nf < 8; nf++) {
            int cb = wn + nf * 8 + t4 * 2;
            if (r0 < N_NODES)
                *(__half2*)(g_h1 + (size_t)r0 * HID + cb) =
                    __floats2half2_rn(acc[mf][nf][0], acc[mf][nf][1]);
            if (r1 < N_NODES)
                *(__half2*)(g_h1 + (size_t)r1 * HID + cb) =
                    __floats2half2_rn(acc[mf][nf][2], acc[mf][nf][3]);
        }
    }
}

// ---------------- layer-1 aggregation + bias + relu -> fp16 a1 ----------------
__global__ void k_agg1(const float* __restrict__ b1) {
    int gw = (blockIdx.x * blockDim.x + threadIdx.x) >> 5;
    if (gw >= N_NODES) return;
    int lane = threadIdx.x & 31;
    const __half* hbase = g_h1;
    int doff = lane * 4;

    float4 selfv = ld_h4(hbase + (size_t)gw * HID + doff);
    float4 acc0 = make_float4(0.f, 0.f, 0.f, 0.f);
    float4 acc1 = make_float4(0.f, 0.f, 0.f, 0.f);

    int beg = g_off[gw];
    int end = beg + g_cnt[gw];
    int e = beg;
    for (; e + 2 <= end; e += 2) {
        int2 e0 = g_edge[e];
        int2 e1 = g_edge[e + 1];
        float w0 = __int_as_float(e0.y), w1 = __int_as_float(e1.y);
        float4 v0 = ld_h4(hbase + (size_t)e0.x * HID + doff);
        float4 v1 = ld_h4(hbase + (size_t)e1.x * HID + doff);
        acc0.x = fmaf(w0, v0.x, acc0.x); acc0.y = fmaf(w0, v0.y, acc0.y);
        acc0.z = fmaf(w0, v0.z, acc0.z); acc0.w = fmaf(w0, v0.w, acc0.w);
        acc1.x = fmaf(w1, v1.x, acc1.x); acc1.y = fmaf(w1, v1.y, acc1.y);
        acc1.z = fmaf(w1, v1.z, acc1.z); acc1.w = fmaf(w1, v1.w, acc1.w);
    }
    if (e < end) {
        int2 e0 = g_edge[e];
        float w0 = __int_as_float(e0.y);
        float4 v0 = ld_h4(hbase + (size_t)e0.x * HID + doff);
        acc0.x = fmaf(w0, v0.x, acc0.x); acc0.y = fmaf(w0, v0.y, acc0.y);
        acc0.z = fmaf(w0, v0.z, acc0.z); acc0.w = fmaf(w0, v0.w, acc0.w);
    }
    float s = g_dinv[gw];
    float s2 = s * s;
    float4 bb = *(const float4*)(b1 + doff);
    float rx = fmaxf(fmaf(s2, selfv.x, acc0.x + acc1.x) + bb.x, 0.f);
    float ry = fmaxf(fmaf(s2, selfv.y, acc0.y + acc1.y) + bb.y, 0.f);
    float rz = fmaxf(fmaf(s2, selfv.z, acc0.z + acc1.z) + bb.z, 0.f);
    float rw = fmaxf(fmaf(s2, selfv.w, acc0.w + acc1.w) + bb.w, 0.f);
    *(__half2*)(g_a1 + (size_t)gw * HID + doff)     = __floats2half2_rn(rx, ry);
    *(__half2*)(g_a1 + (size_t)gw * HID + doff + 2) = __floats2half2_rn(rz, rw);
}

// ---------------- GEMM2: fp16 HMMA, all-cp.async, 2-stage ----------------
// C[100000,64] = a1 @ W2; BM=128 BN=64 BK=32.
__global__ void __launch_bounds__(256, 2) k_gemm2_mma() {
    __shared__ __align__(16) __half sA[2][128 * APAD];
    __shared__ __align__(16) __half sB[2][64 * APAD];

    int tid = threadIdx.x;
    int lane = tid & 31;
    int wid = tid >> 5;
    int wm = (wid & 3) * 32;
    int wn = (wid >> 2) * 32;
    int row0 = blockIdx.x * 128;

    int within = lane & 7, sub = lane >> 3;
    int aRow = within + (sub & 1) * 8;
    int aK   = (sub >> 1) * 8;
    int bN   = within + (sub >> 1) * 8;
    int bK   = (sub & 1) * 8;

    float acc[2][4][4];
#pragma unroll
    for (int mf = 0; mf < 2; mf++)
#pragma unroll
        for (int nf = 0; nf < 4; nf++)
#pragma unroll
            for (int q = 0; q < 4; q++) acc[mf][nf][q] = 0.0f;

    // A tile: 128 rows x 32 halves = 512 chunks, 2/thread (rows clamped in-range)
    auto issueAB = [&](int kt, int stage) {
#pragma unroll
        for (int j = 0; j < 2; j++) {
            int i = tid + j * 256;
            int r = i >> 2, c8 = (i & 3) * 8;
            int gr = row0 + r;
            if (gr >= N_NODES) gr = N_NODES - 1;   // clamp: values unused, stay in-bounds
            cp_async16(&sA[stage][r * APAD + c8], g_a1 + (size_t)gr * HID + kt + c8);
        }
        {   // B tile: 64 rows x 32 halves = 256 chunks, 1/thread
            int n = tid >> 2, c8 = (tid & 3) * 8;
            cp_async16(&sB[stage][n * APAD + c8], g_W2h + (size_t)n * HID + kt + c8);
        }
        CP_COMMIT();
    };

    issueAB(0, 0);
    CP_WAIT(0);
    __syncthreads();

#pragma unroll 1
    for (int t = 0; t < 4; t++) {
        int cur = t & 1, nxt = cur ^ 1;
        if (t < 3) issueAB((t + 1) * 32, nxt);

        uint32_t aB = smem_u32(sA[cur]);
        uint32_t bB = smem_u32(sB[cur]);
#pragma unroll
        for (int kf = 0; kf < 2; kf++) {
            int kk = kf * 16;
            uint32_t af[2][4];
#pragma unroll
            for (int mf = 0; mf < 2; mf++)
                ldm4(af[mf], aB + (uint32_t)((wm + mf * 16 + aRow) * APAD + kk + aK) * 2);
#pragma unroll
            for (int np = 0; np < 2; np++) {
                uint32_t bf[4];
                ldm4(bf, bB + (uint32_t)((wn + np * 16 + bN) * APAD + kk + bK) * 2);
#pragma unroll
                for (int s = 0; s < 2; s++) {
                    int nf = np * 2 + s;
#pragma unroll
                    for (int mf = 0; mf < 2; mf++)
                        mma_f16(acc[mf][nf], af[mf], bf + s * 2);
                }
            }
        }
        if (t < 3) {
            CP_WAIT(0);
            __syncthreads();
        }
    }

    int g = lane >> 2, t4 = lane & 3;
#pragma unroll
    for (int mf = 0; mf < 2; mf++) {
        int r0 = row0 + wm + mf * 16 + g;
        int r1 = r0 + 8;
#pragma unroll
        for (int nf = 0; nf < 4; nf++) {
            int cb = wn + nf * 8 + t4 * 2;
            if (r0 < N_NODES)
                *(__half2*)(g_h2 + (size_t)r0 * OUTD + cb) =
                    __floats2half2_rn(acc[mf][nf][0], acc[mf][nf][1]);
            if (r1 < N_NODES)
                *(__half2*)(g_h2 + (size_t)r1 * OUTD + cb) =
                    __floats2half2_rn(acc[mf][nf][2], acc[mf][nf][3]);
        }
    }
}

// ---------------- layer-2 aggregation ----------------
__global__ void k_agg2(const float* __restrict__ b2, float* __restrict__ out) {
    int gw = (blockIdx.x * blockDim.x + threadIdx.x) >> 5;
    if (gw >= N_NODES) return;
    int lane = threadIdx.x & 31;
    int doff = lane * 2;

    float2 selfv = __half22float2(*(const __half2*)(g_h2 + (size_t)gw * OUTD + doff));
    float2 acc0 = make_float2(0.f, 0.f);
    float2 acc1 = make_float2(0.f, 0.f);

    int beg = g_off[gw];
    int end = beg + g_cnt[gw];
    int e = beg;
    for (; e + 2 <= end; e += 2) {
        int2 e0 = g_edge[e];
        int2 e1 = g_edge[e + 1];
        float w0 = __int_as_float(e0.y), w1 = __int_as_float(e1.y);
        float2 v0 = __half22float2(*(const __half2*)(g_h2 + (size_t)e0.x * OUTD + doff));
        float2 v1 = __half22float2(*(const __half2*)(g_h2 + (size_t)e1.x * OUTD + doff));
        acc0.x = fmaf(w0, v0.x, acc0.x); acc0.y = fmaf(w0, v0.y, acc0.y);
        acc1.x = fmaf(w1, v1.x, acc1.x); acc1.y = fmaf(w1, v1.y, acc1.y);
    }
    if (e < end) {
        int2 e0 = g_edge[e];
        float w0 = __int_as_float(e0.y);
        float2 v0 = __half22float2(*(const __half2*)(g_h2 + (size_t)e0.x * OUTD + doff));
        acc0.x = fmaf(w0, v0.x, acc0.x); acc0.y = fmaf(w0, v0.y, acc0.y);
    }
    float s = g_dinv[gw];
    float s2 = s * s;
    float2 bb = ((const float2*)b2)[lane];
    float2 r = make_float2(fmaf(s2, selfv.x, acc0.x + acc1.x) + bb.x,
                           fmaf(s2, selfv.y, acc0.y + acc1.y) + bb.y);
    *(float2*)(out + (size_t)gw * OUTD + doff) = r;
}

// ---------------- launch ----------------
extern "C" void kernel_launch(void* const* d_in, const int* in_sizes, int n_in,
                              void* d_out, int out_size) {
    const float* x  = (const float*)d_in[0];
    const int*   ei = (const int*)d_in[1];   // int32 (JAX downgrades int64)
    const float* ew = (const float*)d_in[2];
    const float* W1 = (const float*)d_in[3];
    const float* b1 = (const float*)d_in[4];
    const float* W2 = (const float*)d_in[5];
    const float* b2 = (const float*)d_in[6];
    float*       out = (float*)d_out;

    const int* row = ei;
    const int* col = ei + N_EDGES;

    static cudaStream_t s2 = nullptr;
    static cudaEvent_t ev1 = nullptr, ev2 = nullptr;
    if (s2 == nullptr) {
        cudaStreamCreateWithFlags(&s2, cudaStreamNonBlocking);
        cudaEventCreateWithFlags(&ev1, cudaEventDisableTiming);
        cudaEventCreateWithFlags(&ev2, cudaEventDisableTiming);
    }

    k_setup<<<(N_NODES + 255) / 256, 256>>>(W1, W2);                     // main
    cudaEventRecord(ev1, 0);
    cudaStreamWaitEvent(s2, ev1, 0);

    k_hist<<<(N_EDGES / 2 + 255) / 256, 256, 0, s2>>>(col, ew);          // s2
    k_dinvalloc<<<(N_NODES + 255) / 256, 256, 0, s2>>>();                // s2
    k_gemm1_mma<<<(N_NODES + 127) / 128, 256>>>(x);                      // main (profiled)
    k_fill<<<(N_EDGES / 2 + 255) / 256, 256, 0, s2>>>(row, col, ew);     // s2

    cudaEventRecord(ev2, s2);
    cudaStreamWaitEvent(0, ev2, 0);

    k_agg1<<<(N_NODES * 32 + 255) / 256, 256>>>(b1);                     // main
    k_gemm2_mma<<<(N_NODES + 127) / 128, 256>>>();                       // main
    k_agg2<<<(N_NODES * 32 + 255) / 256, 256>>>(b2, out);                // main
}